// round 11
// baseline (speedup 1.0000x reference)
#include <cuda_runtime.h>
#include <cuda_bf16.h>
#include <math.h>
#include <stdint.h>

#define NB 512
#define EPSF 1e-20f
#define BN_EPSF 1e-5f
#define INV_ATTN 0.35355339059327373f   // 1/sqrt(8)

// exp matched to reference (correctly rounded small-arg Taylor; squash-sensitive regime)
__device__ __forceinline__ float exp_matched(float n) {
    if (n < 0.05f) {
        float p = fmaf(n, 1.0f / 120.0f, 1.0f / 24.0f);
        p = fmaf(p, n, 1.0f / 6.0f);
        p = fmaf(p, n, 0.5f);
        return 1.0f + fmaf(n * n, p, n);
    }
    return expf(n);
}

__device__ __forceinline__ uint32_t bfsplit_pack_hi(float x0, float x1, uint32_t& lo) {
    __nv_bfloat16 h0 = __float2bfloat16(x0), h1 = __float2bfloat16(x1);
    __nv_bfloat16 l0 = __float2bfloat16(x0 - __bfloat162float(h0));
    __nv_bfloat16 l1 = __float2bfloat16(x1 - __bfloat162float(h1));
    lo = (uint32_t)__bfloat16_as_ushort(l0) | ((uint32_t)__bfloat16_as_ushort(l1) << 16);
    return (uint32_t)__bfloat16_as_ushort(h0) | ((uint32_t)__bfloat16_as_ushort(h1) << 16);
}

__device__ __forceinline__ uint32_t smem_u32(const void* p) {
    uint32_t a;
    asm("{ .reg .u64 t; cvta.to.shared.u64 t, %1; cvt.u32.u64 %0, t; }" : "=r"(a) : "l"(p));
    return a;
}
__device__ __forceinline__ void cp_async16(uint32_t saddr, const void* gptr) {
    asm volatile("cp.async.cg.shared.global [%0], [%1], 16;" :: "r"(saddr), "l"(gptr));
}
#define CP_COMMIT() asm volatile("cp.async.commit_group;" ::: "memory")
#define CP_WAIT1()  asm volatile("cp.async.wait_group 1;" ::: "memory")
#define CP_WAIT0()  asm volatile("cp.async.wait_group 0;" ::: "memory")

// ---------------- scratch ----------------
__device__ float g_h1[NB * 128 * 19 * 19];     // conv1 out, [b][ci][19x19]
__device__ float g_h2[NB * 81 * 256];          // conv2 out, [b*81+p][co]
__device__ uint32_t g_wbh[256 * 576];          // conv2 weights bf16-hi packed k-pairs [co][k/2]
__device__ uint32_t g_wbl[256 * 576];          // bf16-lo residual

// ---------------- conv1 + bn + relu : one block per image ----------------
__global__ void __launch_bounds__(384) conv1_kernel(
    const float* __restrict__ x, const float* __restrict__ w, const float* __restrict__ cb,
    const float* __restrict__ g, const float* __restrict__ bb,
    const float* __restrict__ m, const float* __restrict__ v)
{
    int b = blockIdx.x, tid = threadIdx.x;
    __shared__ float s_in[39 * 39];
    __shared__ float s_w[128 * 9];
    __shared__ float s_sc[128], s_sh[128];
    const float* xb = x + b * 1521;
    for (int i = tid; i < 1521; i += 384) s_in[i] = xb[i];
    for (int i = tid; i < 1152; i += 384) s_w[i] = w[i];
    if (tid < 128) {
        float inv = g[tid] / sqrtf(v[tid] + BN_EPSF);
        s_sc[tid] = inv;
        s_sh[tid] = cb[tid] * inv + (bb[tid] - m[tid] * inv);
    }
    __syncthreads();
    if (tid < 361) {
        int oy = tid / 19, ox = tid % 19;
        float r[9];
#pragma unroll
        for (int kh = 0; kh < 3; ++kh)
#pragma unroll
            for (int kw = 0; kw < 3; ++kw)
                r[kh * 3 + kw] = s_in[(oy * 2 + kh) * 39 + ox * 2 + kw];
        float* outb = g_h1 + b * 128 * 361 + tid;
#pragma unroll 4
        for (int co = 0; co < 128; ++co) {
            float acc = 0.0f;
#pragma unroll
            for (int k = 0; k < 9; ++k) acc = fmaf(r[k], s_w[co * 9 + k], acc);
            float y = acc * s_sc[co] + s_sh[co];
            outb[co * 361] = y > 0.0f ? y : 0.0f;
        }
    }
}

// ---------------- conv2 weight prep: bf16 hi/lo split, packed k-pairs ----------------
__global__ void wtrans_kernel(const float* __restrict__ w2)
{
    int widx = blockIdx.x * 256 + threadIdx.x;   // 576 blocks -> 147456
    int n = widx / 576, kp = widx % 576;
    uint32_t lo;
    uint32_t hi = bfsplit_pack_hi(w2[n * 1152 + 2 * kp], w2[n * 1152 + 2 * kp + 1], lo);
    g_wbh[widx] = hi;
    g_wbl[widx] = lo;
}

// ---------------- conv2 as implicit GEMM on mma.sync bf16 3-term, pipelined ----------------
// One CTA per 64-row m-tile (648 CTAs -> 4.38 tiles/SM, small wave tail), full N=256.
// 512 threads = 16 warps: warp -> 16-row slab (w>>2), 64-col quarter (w&3);
// 8 n8-subtiles, 32 accums/thread.
// smem words: AH[64*36] AL[64*36] | B[2 buf][hi 256*36 | lo 256*36] | tab | base | sc | sh
#define AH_OFF 0
#define AL_OFF 2304
#define B_OFF 4608
#define B_BUF_STRIDE 18432
#define B_HL_STRIDE 9216
#define TAB_OFF 41472
#define BASE_OFF 42624
#define SC_OFF 42688
#define SH_OFF 42944
#define C2_SMEM_WORDS 43200

__global__ void __launch_bounds__(512, 1) conv2_mma_kernel(
    const float* __restrict__ cb,
    const float* __restrict__ g, const float* __restrict__ bb,
    const float* __restrict__ m, const float* __restrict__ v)
{
    extern __shared__ uint32_t sm[];
    uint32_t* sAh = sm + AH_OFF;          // [64][36]
    uint32_t* sAl = sm + AL_OFF;
    int*   tabi  = (int*)(sm + TAB_OFF);  // [1152]
    int*   basei = (int*)(sm + BASE_OFF); // [64]
    float* ssc   = (float*)(sm + SC_OFF); // [256]
    float* ssh   = (float*)(sm + SH_OFF); // [256]
    const uint32_t sbase = smem_u32(sm);

    const int tid = threadIdx.x;
    const int w = tid >> 5, lane = tid & 31;
    const int gi = lane >> 2, ti = lane & 3;
    const int mt = blockIdx.x;
    const int r0 = (w >> 2) * 16;         // row slab (4 slabs)
    const int c0 = (w & 3) * 64;          // column quarter (4 quarters)

    for (int k = tid; k < 1152; k += 512) {
        int ci = k / 9, r = k - ci * 9;
        tabi[k] = ci * 361 + (r / 3) * 19 + (r % 3);
    }
    if (tid < 64) {
        int mg = mt * 64 + tid;
        int b = mg / 81, p = mg - b * 81;
        basei[tid] = b * 46208 + (p / 9) * 38 + (p % 9) * 2;   // 46208 = 128*361
    }
    if (tid < 256) {
        float inv = g[tid] / sqrtf(v[tid] + BN_EPSF);
        ssc[tid] = inv;
        ssh[tid] = cb[tid] * inv + (bb[tid] - m[tid] * inv);
    }
    __syncthreads();

    float d[8][4];
#pragma unroll
    for (int s = 0; s < 8; ++s)
#pragma unroll
        for (int q = 0; q < 4; ++q) d[s][q] = 0.0f;

    const int am = tid >> 3;             // A: this thread's m row (0..63)
    const int akb = (tid & 7) * 8;       // k sub-range (8 elements)
    const int awb = (tid & 7) * 4;       // word offset (4 words)

    float fr[8];

    // ---- prologue: B(0) cp.async + A(0) gather ----
    {
        // B: 4096 x 16B ops total; 8 per thread
#pragma unroll
        for (int j = 0; j < 8; ++j) {
            int idx = tid + (j << 9);
            int hl = idx >> 11, n = (idx >> 3) & 255, seg = idx & 7;
            const uint32_t* gsrc = (hl ? g_wbl : g_wbh) + n * 576 + seg * 4;
            uint32_t saddr = sbase + (B_OFF + hl * B_HL_STRIDE + n * 36 + seg * 4) * 4;
            cp_async16(saddr, gsrc);
        }
        CP_COMMIT();
        const float* src = g_h1 + basei[am];
        const int* tp = tabi + akb;
#pragma unroll
        for (int j = 0; j < 8; ++j) fr[j] = src[tp[j]];
    }

    for (int ch = 0; ch < 18; ++ch) {
        const int buf = ch & 1;
        // ---- cvt + STS A(ch) ----
        {
            uint32_t* dH = sAh + am * 36 + awb;
            uint32_t* dL = sAl + am * 36 + awb;
#pragma unroll
            for (int j = 0; j < 4; ++j) {
                uint32_t lo;
                uint32_t hi = bfsplit_pack_hi(fr[2 * j], fr[2 * j + 1], lo);
                dH[j] = hi;
                dL[j] = lo;
            }
        }
        if (ch < 17) {
            // ---- prefetch B(ch+1) into other buffer ----
            const int kp0n = (ch + 1) * 32;
#pragma unroll
            for (int j = 0; j < 8; ++j) {
                int idx = tid + (j << 9);
                int hl = idx >> 11, n = (idx >> 3) & 255, seg = idx & 7;
                const uint32_t* gsrc = (hl ? g_wbl : g_wbh) + n * 576 + kp0n + seg * 4;
                uint32_t saddr = sbase + (B_OFF + (buf ^ 1) * B_BUF_STRIDE + hl * B_HL_STRIDE + n * 36 + seg * 4) * 4;
                cp_async16(saddr, gsrc);
            }
            CP_COMMIT();
            // ---- prefetch A(ch+1) gather into regs ----
            const float* src = g_h1 + basei[am];
            const int* tp = tabi + (ch + 1) * 64 + akb;
#pragma unroll
            for (int j = 0; j < 8; ++j) fr[j] = src[tp[j]];
            CP_WAIT1();
        } else {
            CP_WAIT0();
        }
        __syncthreads();

        // ---- MMA: 4 k16-steps x 8 n-subtiles x 3 terms ----
        const uint32_t* sBh = sm + B_OFF + buf * B_BUF_STRIDE;
        const uint32_t* sBl = sBh + B_HL_STRIDE;
        const uint32_t* AhR = sAh + (r0 + gi) * 36;
        const uint32_t* AlR = sAl + (r0 + gi) * 36;
#pragma unroll
        for (int s16 = 0; s16 < 4; ++s16) {
            const int kw = s16 * 8;
            uint32_t ah0 = AhR[kw + ti],          ah1 = AhR[8 * 36 + kw + ti];
            uint32_t ah2 = AhR[kw + ti + 4],      ah3 = AhR[8 * 36 + kw + ti + 4];
            uint32_t al0 = AlR[kw + ti],          al1 = AlR[8 * 36 + kw + ti];
            uint32_t al2 = AlR[kw + ti + 4],      al3 = AlR[8 * 36 + kw + ti + 4];
#pragma unroll
            for (int s = 0; s < 8; ++s) {
                const int br = (c0 + s * 8 + gi) * 36 + kw;
                uint32_t bh0 = sBh[br + ti], bh1 = sBh[br + ti + 4];
                uint32_t bl0 = sBl[br + ti], bl1 = sBl[br + ti + 4];
                asm volatile(
                    "mma.sync.aligned.m16n8k16.row.col.f32.bf16.bf16.f32 "
                    "{%0,%1,%2,%3}, {%4,%5,%6,%7}, {%8,%9}, {%0,%1,%2,%3};"
                    : "+f"(d[s][0]), "+f"(d[s][1]), "+f"(d[s][2]), "+f"(d[s][3])
                    : "r"(ah0), "r"(ah1), "r"(ah2), "r"(ah3), "r"(bh0), "r"(bh1));
                asm volatile(
                    "mma.sync.aligned.m16n8k16.row.col.f32.bf16.bf16.f32 "
                    "{%0,%1,%2,%3}, {%4,%5,%6,%7}, {%8,%9}, {%0,%1,%2,%3};"
                    : "+f"(d[s][0]), "+f"(d[s][1]), "+f"(d[s][2]), "+f"(d[s][3])
                    : "r"(ah0), "r"(ah1), "r"(ah2), "r"(ah3), "r"(bl0), "r"(bl1));
                asm volatile(
                    "mma.sync.aligned.m16n8k16.row.col.f32.bf16.bf16.f32 "
                    "{%0,%1,%2,%3}, {%4,%5,%6,%7}, {%8,%9}, {%0,%1,%2,%3};"
                    : "+f"(d[s][0]), "+f"(d[s][1]), "+f"(d[s][2]), "+f"(d[s][3])
                    : "r"(al0), "r"(al1), "r"(al2), "r"(al3), "r"(bh0), "r"(bh1));
            }
        }
        __syncthreads();
    }

    // ---- epilogue: bn + relu -> g_h2[mg][co] ----
    const int mrow0 = mt * 64 + r0 + gi;
#pragma unroll
    for (int s = 0; s < 8; ++s) {
        int cl = c0 + s * 8 + 2 * ti;
        float sc0 = ssc[cl], sc1 = ssc[cl + 1];
        float sh0 = ssh[cl], sh1 = ssh[cl + 1];
        float v0 = d[s][0] * sc0 + sh0; v0 = v0 > 0.0f ? v0 : 0.0f;
        float v1 = d[s][1] * sc1 + sh1; v1 = v1 > 0.0f ? v1 : 0.0f;
        float v2 = d[s][2] * sc0 + sh0; v2 = v2 > 0.0f ? v2 : 0.0f;
        float v3 = d[s][3] * sc1 + sh1; v3 = v3 > 0.0f ? v3 : 0.0f;
        *(float2*)(g_h2 + (size_t)mrow0 * 256 + cl)       = make_float2(v0, v1);
        *(float2*)(g_h2 + (size_t)(mrow0 + 8) * 256 + cl) = make_float2(v2, v3);
    }
}

// ---------------- fused conv3 (depthwise 9x9) + squash + fccaps x3 ----------------
__device__ __forceinline__ void fccaps_layer(
    int nl, int nh, int dl, int dh, const float* __restrict__ W,
    float* sU, float* sUhat, float* sS, float* sA, int tid)
{
    int tot = nl * nh * dh;
    for (int idx = tid; idx < tot; idx += 256) {
        int i = idx / (nh * dh);
        int r = idx % (nh * dh);
        int k = r / dh, l = r % dh;
        const float* wp = W + ((i * nh + k) * dl) * dh + l;
        float a = 0.0f;
        for (int j = 0; j < dl; ++j) a = fmaf(sU[i * dl + j], wp[j * dh], a);
        sUhat[idx] = a;
    }
    __syncthreads();
    for (int idx = tid; idx < nh * dh; idx += 256) {
        int k = idx / dh, l = idx % dh;
        float s = 0.0f;
        for (int i = 0; i < nl; ++i) s += sUhat[(i * nh + k) * dh + l];
        sS[idx] = s;
    }
    __syncthreads();
    for (int idx = tid; idx < nl * nh; idx += 256) {
        int i = idx / nh, k = idx % nh;
        float a = 0.0f;
        for (int l = 0; l < dh; ++l) a = fmaf(sS[k * dh + l], sUhat[(i * nh + k) * dh + l], a);
        sA[idx] = a * INV_ATTN;
    }
    __syncthreads();
    if (tid < nl) {
        float mx = -1e30f;
        for (int k = 0; k < nh; ++k) mx = fmaxf(mx, sA[tid * nh + k]);
        float s = 0.0f;
        for (int k = 0; k < nh; ++k) { float e = expf(sA[tid * nh + k] - mx); sA[tid * nh + k] = e; s += e; }
        float is = 1.0f / s;
        for (int k = 0; k < nh; ++k) sA[tid * nh + k] *= is;
    }
    __syncthreads();
    for (int idx = tid; idx < nh * dh; idx += 256) {
        int k = idx / dh, l = idx % dh;
        float a = 0.0f;
        for (int i = 0; i < nl; ++i) a = fmaf(sA[i * nh + k], sUhat[(i * nh + k) * dh + l], a);
        sS[idx] = a;
    }
    __syncthreads();
    for (int idx = tid; idx < nh * dh; idx += 256) {
        int k = idx / dh;
        float nsq = 0.0f;
        for (int l = 0; l < dh; ++l) { float t = sS[k * dh + l]; nsq = fmaf(t, t, nsq); }
        float nrm = sqrtf(nsq);
        float t1 = 1.0f - 1.0f / (exp_matched(nrm) + EPSF);
        sU[idx] = t1 * (sS[idx] / (nrm + EPSF));
    }
    __syncthreads();
}

__global__ void caps_kernel(const float* __restrict__ w3, const float* __restrict__ b3,
                            const float* __restrict__ W1,
                            const float* __restrict__ W2,
                            const float* __restrict__ W3,
                            float* __restrict__ out)
{
    int b = blockIdx.x, tid = threadIdx.x;
    __shared__ float sU[512];
    __shared__ float sUhat[8192];
    __shared__ float sS[512];
    __shared__ float sA[1024];

    // ---- fused conv3 (depthwise 9x9) + squash -> sU ----
    {
        const float* h2b = g_h2 + b * 81 * 256;
        float acc = 0.0f;
#pragma unroll
        for (int p = 0; p < 81; ++p)
            acc = fmaf(h2b[p * 256 + tid], w3[tid * 81 + p], acc);
        acc += b3[tid];

        float sq = acc * acc;
        sq += __shfl_xor_sync(0xffffffffu, sq, 4);
        sq += __shfl_xor_sync(0xffffffffu, sq, 2);
        sq += __shfl_xor_sync(0xffffffffu, sq, 1);
        float nrm = sqrtf(sq);
        float t1 = 1.0f - 1.0f / (exp_matched(nrm) + EPSF);
        sU[tid] = t1 * (acc / (nrm + EPSF));
        sU[256 + tid] = 0.0f;
    }
    __syncthreads();

    fccaps_layer(32, 32, 8, 8, W1, sU, sUhat, sS, sA, tid);
    fccaps_layer(32, 32, 8, 8, W2, sU, sUhat, sS, sA, tid);
    fccaps_layer(32, 10, 8, 16, W3, sU, sUhat, sS, sA, tid);

    if (tid < 160) out[b * 160 + tid] = sU[tid];
}

// ---------------- launch ----------------
extern "C" void kernel_launch(void* const* d_in, const int* in_sizes, int n_in,
                              void* d_out, int out_size)
{
    const float* x       = (const float*)d_in[0];
    const float* conv1_w = (const float*)d_in[1];
    const float* conv1_b = (const float*)d_in[2];
    const float* bn1_g   = (const float*)d_in[3];
    const float* bn1_b   = (const float*)d_in[4];
    const float* bn1_m   = (const float*)d_in[5];
    const float* bn1_v   = (const float*)d_in[6];
    const float* conv2_w = (const float*)d_in[7];
    const float* conv2_b = (const float*)d_in[8];
    const float* bn2_g   = (const float*)d_in[9];
    const float* bn2_b   = (const float*)d_in[10];
    const float* bn2_m   = (const float*)d_in[11];
    const float* bn2_v   = (const float*)d_in[12];
    const float* conv3_w = (const float*)d_in[13];
    const float* conv3_b = (const float*)d_in[14];
    const float* W1      = (const float*)d_in[15];
    const float* W2      = (const float*)d_in[16];
    const float* W3      = (const float*)d_in[17];
    float* out = (float*)d_out;

    cudaFuncSetAttribute(conv2_mma_kernel, cudaFuncAttributeMaxDynamicSharedMemorySize,
                         C2_SMEM_WORDS * (int)sizeof(uint32_t));

    conv1_kernel<<<NB, 384>>>(x, conv1_w, conv1_b, bn1_g, bn1_b, bn1_m, bn1_v);
    wtrans_kernel<<<576, 256>>>(conv2_w);
    conv2_mma_kernel<<<648, 512, C2_SMEM_WORDS * sizeof(uint32_t)>>>(
        conv2_b, bn2_g, bn2_b, bn2_m, bn2_v);
    caps_kernel<<<NB, 256>>>(conv3_w, conv3_b, W1, W2, W3, out);
}

// round 13
// speedup vs baseline: 1.2672x; 1.2672x over previous
#include <cuda_runtime.h>
#include <cuda_bf16.h>
#include <math.h>
#include <stdint.h>

#define NB 512
#define EPSF 1e-20f
#define BN_EPSF 1e-5f
#define INV_ATTN 0.35355339059327373f   // 1/sqrt(8)

__device__ __forceinline__ float exp_matched(float n) {
    if (n < 0.05f) {
        float p = fmaf(n, 1.0f / 120.0f, 1.0f / 24.0f);
        p = fmaf(p, n, 1.0f / 6.0f);
        p = fmaf(p, n, 0.5f);
        return 1.0f + fmaf(n * n, p, n);
    }
    return expf(n);
}

__device__ __forceinline__ uint32_t bfsplit_pack_hi(float x0, float x1, uint32_t& lo) {
    __nv_bfloat16 h0 = __float2bfloat16(x0), h1 = __float2bfloat16(x1);
    __nv_bfloat16 l0 = __float2bfloat16(x0 - __bfloat162float(h0));
    __nv_bfloat16 l1 = __float2bfloat16(x1 - __bfloat162float(h1));
    lo = (uint32_t)__bfloat16_as_ushort(l0) | ((uint32_t)__bfloat16_as_ushort(l1) << 16);
    return (uint32_t)__bfloat16_as_ushort(h0) | ((uint32_t)__bfloat16_as_ushort(h1) << 16);
}

__device__ __forceinline__ uint32_t smem_u32(const void* p) {
    uint32_t a;
    asm("{ .reg .u64 t; cvta.to.shared.u64 t, %1; cvt.u32.u64 %0, t; }" : "=r"(a) : "l"(p));
    return a;
}
__device__ __forceinline__ void cp_async16(uint32_t saddr, const void* gptr) {
    asm volatile("cp.async.cg.shared.global [%0], [%1], 16;" :: "r"(saddr), "l"(gptr));
}
#define CP_COMMIT() asm volatile("cp.async.commit_group;" ::: "memory")
#define CP_WAIT1()  asm volatile("cp.async.wait_group 1;" ::: "memory")
#define CP_WAIT0()  asm volatile("cp.async.wait_group 0;" ::: "memory")

// ---------------- scratch (device globals; referenced ONLY from device code) ----------------
__device__ float g_h1[NB * 128 * 19 * 19];     // conv1 out
__device__ float g_h2[NB * 81 * 256];          // conv2 out, [b*81+p][co]
__device__ uint32_t g_wbh[256 * 576];
__device__ uint32_t g_wbl[256 * 576];
__device__ float g_u[NB * 256];                // current layer capsule input
__device__ float g_uhat[NB * 8192];            // U_hat buffer ([b][i][k*DH+l])

// ---------------- conv1 + bn + relu : one block per image ----------------
__global__ void __launch_bounds__(384) conv1_kernel(
    const float* __restrict__ x, const float* __restrict__ w, const float* __restrict__ cb,
    const float* __restrict__ g, const float* __restrict__ bb,
    const float* __restrict__ m, const float* __restrict__ v)
{
    int b = blockIdx.x, tid = threadIdx.x;
    __shared__ float s_in[39 * 39];
    __shared__ float s_w[128 * 9];
    __shared__ float s_sc[128], s_sh[128];
    const float* xb = x + b * 1521;
    for (int i = tid; i < 1521; i += 384) s_in[i] = xb[i];
    for (int i = tid; i < 1152; i += 384) s_w[i] = w[i];
    if (tid < 128) {
        float inv = g[tid] / sqrtf(v[tid] + BN_EPSF);
        s_sc[tid] = inv;
        s_sh[tid] = cb[tid] * inv + (bb[tid] - m[tid] * inv);
    }
    __syncthreads();
    if (tid < 361) {
        int oy = tid / 19, ox = tid % 19;
        float r[9];
#pragma unroll
        for (int kh = 0; kh < 3; ++kh)
#pragma unroll
            for (int kw = 0; kw < 3; ++kw)
                r[kh * 3 + kw] = s_in[(oy * 2 + kh) * 39 + ox * 2 + kw];
        float* outb = g_h1 + b * 128 * 361 + tid;
#pragma unroll 4
        for (int co = 0; co < 128; ++co) {
            float acc = 0.0f;
#pragma unroll
            for (int k = 0; k < 9; ++k) acc = fmaf(r[k], s_w[co * 9 + k], acc);
            float y = acc * s_sc[co] + s_sh[co];
            outb[co * 361] = y > 0.0f ? y : 0.0f;
        }
    }
}

// ---------------- conv2 weight prep ----------------
__global__ void wtrans_kernel(const float* __restrict__ w2)
{
    int widx = blockIdx.x * 256 + threadIdx.x;
    int n = widx / 576, kp = widx % 576;
    uint32_t lo;
    uint32_t hi = bfsplit_pack_hi(w2[n * 1152 + 2 * kp], w2[n * 1152 + 2 * kp + 1], lo);
    g_wbh[widx] = hi;
    g_wbl[widx] = lo;
}

// ---------------- conv2 implicit GEMM (128-row m-tile, N=256) ----------------
#define AH_OFF 0
#define AL_OFF 4608
#define B_OFF 9216
#define B_BUF_STRIDE 18432
#define B_HL_STRIDE 9216
#define TAB_OFF 46080
#define BASE_OFF 47232
#define SC_OFF 47360
#define SH_OFF 47616
#define C2_SMEM_WORDS 47872

__global__ void __launch_bounds__(512, 1) conv2_mma_kernel(
    const float* __restrict__ cb,
    const float* __restrict__ g, const float* __restrict__ bb,
    const float* __restrict__ m, const float* __restrict__ v)
{
    extern __shared__ uint32_t sm[];
    uint32_t* sAh = sm + AH_OFF;
    uint32_t* sAl = sm + AL_OFF;
    int*   tabi  = (int*)(sm + TAB_OFF);
    int*   basei = (int*)(sm + BASE_OFF);
    float* ssc   = (float*)(sm + SC_OFF);
    float* ssh   = (float*)(sm + SH_OFF);
    const uint32_t sbase = smem_u32(sm);

    const int tid = threadIdx.x;
    const int w = tid >> 5, lane = tid & 31;
    const int gi = lane >> 2, ti = lane & 3;
    const int mt = blockIdx.x;
    const int r0 = (w >> 1) * 16;
    const int c0 = (w & 1) * 128;

    for (int k = tid; k < 1152; k += 512) {
        int ci = k / 9, r = k - ci * 9;
        tabi[k] = ci * 361 + (r / 3) * 19 + (r % 3);
    }
    if (tid < 128) {
        int mg = mt * 128 + tid;
        int b = mg / 81, p = mg - b * 81;
        basei[tid] = b * 46208 + (p / 9) * 38 + (p % 9) * 2;
    }
    if (tid < 256) {
        float inv = g[tid] / sqrtf(v[tid] + BN_EPSF);
        ssc[tid] = inv;
        ssh[tid] = cb[tid] * inv + (bb[tid] - m[tid] * inv);
    }
    __syncthreads();

    float d[16][4];
#pragma unroll
    for (int s = 0; s < 16; ++s)
#pragma unroll
        for (int q = 0; q < 4; ++q) d[s][q] = 0.0f;

    const int am = tid >> 2;
    const int akb = (tid & 3) * 16;
    const int awb = akb >> 1;

    float fr[16];

    {
#pragma unroll
        for (int j = 0; j < 8; ++j) {
            int idx = tid + (j << 9);
            int hl = idx >> 11, n = (idx >> 3) & 255, seg = idx & 7;
            const uint32_t* gsrc = (hl ? g_wbl : g_wbh) + n * 576 + seg * 4;
            uint32_t saddr = sbase + (B_OFF + hl * B_HL_STRIDE + n * 36 + seg * 4) * 4;
            cp_async16(saddr, gsrc);
        }
        CP_COMMIT();
        const float* src = g_h1 + basei[am];
        const int* tp = tabi + akb;
#pragma unroll
        for (int j = 0; j < 16; ++j) fr[j] = src[tp[j]];
    }

    for (int ch = 0; ch < 18; ++ch) {
        const int buf = ch & 1;
        {
            uint32_t* dH = sAh + am * 36 + awb;
            uint32_t* dL = sAl + am * 36 + awb;
#pragma unroll
            for (int j = 0; j < 8; ++j) {
                uint32_t lo;
                uint32_t hi = bfsplit_pack_hi(fr[2 * j], fr[2 * j + 1], lo);
                dH[j] = hi;
                dL[j] = lo;
            }
        }
        if (ch < 17) {
            const int kp0n = (ch + 1) * 32;
#pragma unroll
            for (int j = 0; j < 8; ++j) {
                int idx = tid + (j << 9);
                int hl = idx >> 11, n = (idx >> 3) & 255, seg = idx & 7;
                const uint32_t* gsrc = (hl ? g_wbl : g_wbh) + n * 576 + kp0n + seg * 4;
                uint32_t saddr = sbase + (B_OFF + (buf ^ 1) * B_BUF_STRIDE + hl * B_HL_STRIDE + n * 36 + seg * 4) * 4;
                cp_async16(saddr, gsrc);
            }
            CP_COMMIT();
            const float* src = g_h1 + basei[am];
            const int* tp = tabi + (ch + 1) * 64 + akb;
#pragma unroll
            for (int j = 0; j < 16; ++j) fr[j] = src[tp[j]];
            CP_WAIT1();
        } else {
            CP_WAIT0();
        }
        __syncthreads();

        const uint32_t* sBh = sm + B_OFF + buf * B_BUF_STRIDE;
        const uint32_t* sBl = sBh + B_HL_STRIDE;
        const uint32_t* AhR = sAh + (r0 + gi) * 36;
        const uint32_t* AlR = sAl + (r0 + gi) * 36;
#pragma unroll
        for (int s16 = 0; s16 < 4; ++s16) {
            const int kw = s16 * 8;
            uint32_t ah0 = AhR[kw + ti],          ah1 = AhR[8 * 36 + kw + ti];
            uint32_t ah2 = AhR[kw + ti + 4],      ah3 = AhR[8 * 36 + kw + ti + 4];
            uint32_t al0 = AlR[kw + ti],          al1 = AlR[8 * 36 + kw + ti];
            uint32_t al2 = AlR[kw + ti + 4],      al3 = AlR[8 * 36 + kw + ti + 4];
#pragma unroll
            for (int s = 0; s < 16; ++s) {
                const int br = (c0 + s * 8 + gi) * 36 + kw;
                uint32_t bh0 = sBh[br + ti], bh1 = sBh[br + ti + 4];
                uint32_t bl0 = sBl[br + ti], bl1 = sBl[br + ti + 4];
                asm volatile(
                    "mma.sync.aligned.m16n8k16.row.col.f32.bf16.bf16.f32 "
                    "{%0,%1,%2,%3}, {%4,%5,%6,%7}, {%8,%9}, {%0,%1,%2,%3};"
                    : "+f"(d[s][0]), "+f"(d[s][1]), "+f"(d[s][2]), "+f"(d[s][3])
                    : "r"(ah0), "r"(ah1), "r"(ah2), "r"(ah3), "r"(bh0), "r"(bh1));
                asm volatile(
                    "mma.sync.aligned.m16n8k16.row.col.f32.bf16.bf16.f32 "
                    "{%0,%1,%2,%3}, {%4,%5,%6,%7}, {%8,%9}, {%0,%1,%2,%3};"
                    : "+f"(d[s][0]), "+f"(d[s][1]), "+f"(d[s][2]), "+f"(d[s][3])
                    : "r"(ah0), "r"(ah1), "r"(ah2), "r"(ah3), "r"(bl0), "r"(bl1));
                asm volatile(
                    "mma.sync.aligned.m16n8k16.row.col.f32.bf16.bf16.f32 "
                    "{%0,%1,%2,%3}, {%4,%5,%6,%7}, {%8,%9}, {%0,%1,%2,%3};"
                    : "+f"(d[s][0]), "+f"(d[s][1]), "+f"(d[s][2]), "+f"(d[s][3])
                    : "r"(al0), "r"(al1), "r"(al2), "r"(al3), "r"(bh0), "r"(bh1));
            }
        }
        __syncthreads();
    }

    const int mrow0 = mt * 128 + r0 + gi;
#pragma unroll
    for (int s = 0; s < 16; ++s) {
        int cl = c0 + s * 8 + 2 * ti;
        float sc0 = ssc[cl], sc1 = ssc[cl + 1];
        float sh0 = ssh[cl], sh1 = ssh[cl + 1];
        float v0 = d[s][0] * sc0 + sh0; v0 = v0 > 0.0f ? v0 : 0.0f;
        float v1 = d[s][1] * sc1 + sh1; v1 = v1 > 0.0f ? v1 : 0.0f;
        float v2 = d[s][2] * sc0 + sh0; v2 = v2 > 0.0f ? v2 : 0.0f;
        float v3 = d[s][3] * sc1 + sh1; v3 = v3 > 0.0f ? v3 : 0.0f;
        *(float2*)(g_h2 + (size_t)mrow0 * 256 + cl)       = make_float2(v0, v1);
        *(float2*)(g_h2 + (size_t)(mrow0 + 8) * 256 + cl) = make_float2(v2, v3);
    }
}

// ---------------- conv3 (depthwise 9x9) + squash -> g_u ----------------
__global__ void conv3s_kernel(const float* __restrict__ w3, const float* __restrict__ b3)
{
    int b = blockIdx.x, c = threadIdx.x;
    const float* h2b = g_h2 + b * 81 * 256;
    float acc = 0.0f;
#pragma unroll
    for (int p = 0; p < 81; ++p)
        acc = fmaf(h2b[p * 256 + c], w3[c * 81 + p], acc);
    acc += b3[c];

    float sq = acc * acc;
    sq += __shfl_xor_sync(0xffffffffu, sq, 4);
    sq += __shfl_xor_sync(0xffffffffu, sq, 2);
    sq += __shfl_xor_sync(0xffffffffu, sq, 1);
    float nrm = sqrtf(sq);
    float t1 = 1.0f - 1.0f / (exp_matched(nrm) + EPSF);
    g_u[b * 256 + c] = t1 * (acc / (nrm + EPSF));
}

// ---------------- U_hat GEMM: grid (32 i, 8 batch-chunks of 64), 256 threads ----------------
// Reads g_u, writes g_uhat (device globals — no host-passed scratch pointers).
template<int NH, int DH>
__global__ void __launch_bounds__(256) uhat_kernel(const float* __restrict__ W)
{
    constexpr int NHDH = NH * DH;
    __shared__ float sW[8 * NHDH];     // [j][k*DH+l]
    __shared__ float sUb[64 * 8];      // [bb][j]
    const int i = blockIdx.x;
    const int b0 = blockIdx.y * 64;
    const int tid = threadIdx.x;

    for (int idx = tid; idx < 8 * NHDH; idx += 256) {
        int k = idx / (8 * DH);
        int r = idx % (8 * DH);
        int j = r / DH, l = r % DH;
        sW[j * NHDH + k * DH + l] = W[i * NH * 8 * DH + idx];
    }
    for (int idx = tid; idx < 512; idx += 256) {
        int bb = idx >> 3, j = idx & 7;
        sUb[idx] = g_u[(b0 + bb) * 256 + i * 8 + j];
    }
    __syncthreads();

    if (tid < NHDH) {
        float wr[8];
#pragma unroll
        for (int j = 0; j < 8; ++j) wr[j] = sW[j * NHDH + tid];
        float* dst = g_uhat + (size_t)b0 * (32 * NHDH) + i * NHDH + tid;
#pragma unroll 4
        for (int bb = 0; bb < 64; ++bb) {
            const float* u = sUb + bb * 8;
            float a = 0.0f;
#pragma unroll
            for (int j = 0; j < 8; ++j) a = fmaf(u[j], wr[j], a);
            dst[(size_t)bb * (32 * NHDH)] = a;
        }
    }
}

// ---------------- attention + squash: one block per batch ----------------
// Reads g_uhat; writes g_u (intermediate layers) or `out` (final layer).
template<int NH, int DH, bool FINAL>
__global__ void __launch_bounds__(256) attn_kernel(float* __restrict__ outp)
{
    constexpr int NHDH = NH * DH;
    constexpr int NL = 32;
    __shared__ float sUhat[NL * NHDH];
    __shared__ float sS[NHDH];
    __shared__ float sA[NL * NH];
    const int b = blockIdx.x, tid = threadIdx.x;

    {
        const float4* src = (const float4*)(g_uhat + (size_t)b * (NL * NHDH));
        float4* sd = (float4*)sUhat;
        for (int idx = tid; idx < NL * NHDH / 4; idx += 256) sd[idx] = src[idx];
    }
    __syncthreads();

    if (tid < NHDH) {
        float s = 0.0f;
#pragma unroll
        for (int i = 0; i < NL; ++i) s += sUhat[i * NHDH + tid];
        sS[tid] = s;
    }
    __syncthreads();

    for (int idx = tid; idx < NL * NH; idx += 256) {
        int i = idx / NH, k = idx % NH;
        float a = 0.0f;
#pragma unroll
        for (int l = 0; l < DH; ++l) a = fmaf(sS[k * DH + l], sUhat[i * NHDH + k * DH + l], a);
        sA[idx] = a * INV_ATTN;
    }
    __syncthreads();

    {
        int wid = tid >> 5, lane = tid & 31;
#pragma unroll
        for (int q = 0; q < 4; ++q) {
            int i = wid * 4 + q;
            float val = (lane < NH) ? sA[i * NH + lane] : -1e30f;
            float mx = val;
#pragma unroll
            for (int o = 16; o; o >>= 1) mx = fmaxf(mx, __shfl_xor_sync(0xffffffffu, mx, o));
            float e = (lane < NH) ? expf(val - mx) : 0.0f;
            float sum = e;
#pragma unroll
            for (int o = 16; o; o >>= 1) sum += __shfl_xor_sync(0xffffffffu, sum, o);
            if (lane < NH) sA[i * NH + lane] = e / sum;
        }
    }
    __syncthreads();

    if (tid < NHDH) {
        int k = tid / DH;
        float acc = 0.0f;
#pragma unroll
        for (int i = 0; i < NL; ++i) acc = fmaf(sA[i * NH + k], sUhat[i * NHDH + tid], acc);
        float sq = acc * acc;
#pragma unroll
        for (int o = DH / 2; o; o >>= 1) sq += __shfl_xor_sync(0xffffffffu, sq, o);
        float nrm = sqrtf(sq);
        float t1 = 1.0f - 1.0f / (exp_matched(nrm) + EPSF);
        float val = t1 * (acc / (nrm + EPSF));
        if (FINAL) outp[(size_t)b * NHDH + tid] = val;
        else       g_u[(size_t)b * 256 + tid] = val;
    }
}

// ---------------- launch ----------------
extern "C" void kernel_launch(void* const* d_in, const int* in_sizes, int n_in,
                              void* d_out, int out_size)
{
    const float* x       = (const float*)d_in[0];
    const float* conv1_w = (const float*)d_in[1];
    const float* conv1_b = (const float*)d_in[2];
    const float* bn1_g   = (const float*)d_in[3];
    const float* bn1_b   = (const float*)d_in[4];
    const float* bn1_m   = (const float*)d_in[5];
    const float* bn1_v   = (const float*)d_in[6];
    const float* conv2_w = (const float*)d_in[7];
    const float* conv2_b = (const float*)d_in[8];
    const float* bn2_g   = (const float*)d_in[9];
    const float* bn2_b   = (const float*)d_in[10];
    const float* bn2_m   = (const float*)d_in[11];
    const float* bn2_v   = (const float*)d_in[12];
    const float* conv3_w = (const float*)d_in[13];
    const float* conv3_b = (const float*)d_in[14];
    const float* W1      = (const float*)d_in[15];
    const float* W2      = (const float*)d_in[16];
    const float* W3      = (const float*)d_in[17];
    float* out = (float*)d_out;

    cudaFuncSetAttribute(conv2_mma_kernel, cudaFuncAttributeMaxDynamicSharedMemorySize,
                         C2_SMEM_WORDS * (int)sizeof(uint32_t));

    conv1_kernel<<<NB, 384>>>(x, conv1_w, conv1_b, bn1_g, bn1_b, bn1_m, bn1_v);
    wtrans_kernel<<<576, 256>>>(conv2_w);
    conv2_mma_kernel<<<324, 512, C2_SMEM_WORDS * sizeof(uint32_t)>>>(
        conv2_b, bn2_g, bn2_b, bn2_m, bn2_v);
    conv3s_kernel<<<NB, 256>>>(conv3_w, conv3_b);

    uhat_kernel<32, 8><<<dim3(32, 8), 256>>>(W1);
    attn_kernel<32, 8, false><<<NB, 256>>>(nullptr);
    uhat_kernel<32, 8><<<dim3(32, 8), 256>>>(W2);
    attn_kernel<32, 8, false><<<NB, 256>>>(nullptr);
    uhat_kernel<10, 16><<<dim3(32, 8), 256>>>(W3);
    attn_kernel<10, 16, true><<<NB, 256>>>(out);
}

// round 14
// speedup vs baseline: 1.2807x; 1.0106x over previous
#include <cuda_runtime.h>
#include <cuda_bf16.h>
#include <math.h>
#include <stdint.h>

#define NB 512
#define EPSF 1e-20f
#define BN_EPSF 1e-5f
#define INV_ATTN 0.35355339059327373f   // 1/sqrt(8)

__device__ __forceinline__ float exp_matched(float n) {
    if (n < 0.05f) {
        float p = fmaf(n, 1.0f / 120.0f, 1.0f / 24.0f);
        p = fmaf(p, n, 1.0f / 6.0f);
        p = fmaf(p, n, 0.5f);
        return 1.0f + fmaf(n * n, p, n);
    }
    return expf(n);
}

__device__ __forceinline__ uint32_t bfsplit_pack_hi(float x0, float x1, uint32_t& lo) {
    __nv_bfloat16 h0 = __float2bfloat16(x0), h1 = __float2bfloat16(x1);
    __nv_bfloat16 l0 = __float2bfloat16(x0 - __bfloat162float(h0));
    __nv_bfloat16 l1 = __float2bfloat16(x1 - __bfloat162float(h1));
    lo = (uint32_t)__bfloat16_as_ushort(l0) | ((uint32_t)__bfloat16_as_ushort(l1) << 16);
    return (uint32_t)__bfloat16_as_ushort(h0) | ((uint32_t)__bfloat16_as_ushort(h1) << 16);
}

__device__ __forceinline__ uint32_t smem_u32(const void* p) {
    uint32_t a;
    asm("{ .reg .u64 t; cvta.to.shared.u64 t, %1; cvt.u32.u64 %0, t; }" : "=r"(a) : "l"(p));
    return a;
}
__device__ __forceinline__ void cp_async16(uint32_t saddr, const void* gptr) {
    asm volatile("cp.async.cg.shared.global [%0], [%1], 16;" :: "r"(saddr), "l"(gptr));
}
#define CP_COMMIT() asm volatile("cp.async.commit_group;" ::: "memory")
#define CP_WAIT1()  asm volatile("cp.async.wait_group 1;" ::: "memory")
#define CP_WAIT0()  asm volatile("cp.async.wait_group 0;" ::: "memory")

// ---------------- scratch (device globals; referenced ONLY from device code) ----------------
__device__ float g_h1[NB * 128 * 19 * 19];     // conv1 out
__device__ float g_h2[NB * 81 * 256];          // conv2 out, [b*81+p][co]
__device__ uint32_t g_wbh[256 * 576];
__device__ uint32_t g_wbl[256 * 576];
__device__ float g_u[NB * 256];                // current layer capsule input
__device__ float g_uhat[NB * 8192];            // U_hat buffer ([b][i][k*DH+l])

// ---------------- conv1 + bn + relu : grid (batch, 4 co-groups) ----------------
__global__ void __launch_bounds__(384) conv1_kernel(
    const float* __restrict__ x, const float* __restrict__ w, const float* __restrict__ cb,
    const float* __restrict__ g, const float* __restrict__ bb,
    const float* __restrict__ m, const float* __restrict__ v)
{
    int b = blockIdx.x, co0 = blockIdx.y * 32, tid = threadIdx.x;
    __shared__ float s_in[39 * 39];
    __shared__ float s_w[32 * 9];
    __shared__ float s_sc[32], s_sh[32];
    const float* xb = x + b * 1521;
    for (int i = tid; i < 1521; i += 384) s_in[i] = xb[i];
    if (tid < 288) s_w[tid] = w[co0 * 9 + tid];
    if (tid < 32) {
        int co = co0 + tid;
        float inv = g[co] / sqrtf(v[co] + BN_EPSF);
        s_sc[tid] = inv;
        s_sh[tid] = cb[co] * inv + (bb[co] - m[co] * inv);
    }
    __syncthreads();
    if (tid < 361) {
        int oy = tid / 19, ox = tid % 19;
        float r[9];
#pragma unroll
        for (int kh = 0; kh < 3; ++kh)
#pragma unroll
            for (int kw = 0; kw < 3; ++kw)
                r[kh * 3 + kw] = s_in[(oy * 2 + kh) * 39 + ox * 2 + kw];
        float* outb = g_h1 + b * 128 * 361 + co0 * 361 + tid;
#pragma unroll 4
        for (int cl = 0; cl < 32; ++cl) {
            float acc = 0.0f;
#pragma unroll
            for (int k = 0; k < 9; ++k) acc = fmaf(r[k], s_w[cl * 9 + k], acc);
            float y = acc * s_sc[cl] + s_sh[cl];
            outb[cl * 361] = y > 0.0f ? y : 0.0f;
        }
    }
}

// ---------------- conv2 weight prep ----------------
__global__ void wtrans_kernel(const float* __restrict__ w2)
{
    int widx = blockIdx.x * 256 + threadIdx.x;
    int n = widx / 576, kp = widx % 576;
    uint32_t lo;
    uint32_t hi = bfsplit_pack_hi(w2[n * 1152 + 2 * kp], w2[n * 1152 + 2 * kp + 1], lo);
    g_wbh[widx] = hi;
    g_wbl[widx] = lo;
}

// ---------------- conv2 implicit GEMM (128-row m-tile, N=256) — FROZEN from R13 ----------------
#define AH_OFF 0
#define AL_OFF 4608
#define B_OFF 9216
#define B_BUF_STRIDE 18432
#define B_HL_STRIDE 9216
#define TAB_OFF 46080
#define BASE_OFF 47232
#define SC_OFF 47360
#define SH_OFF 47616
#define C2_SMEM_WORDS 47872

__global__ void __launch_bounds__(512, 1) conv2_mma_kernel(
    const float* __restrict__ cb,
    const float* __restrict__ g, const float* __restrict__ bb,
    const float* __restrict__ m, const float* __restrict__ v)
{
    extern __shared__ uint32_t sm[];
    uint32_t* sAh = sm + AH_OFF;
    uint32_t* sAl = sm + AL_OFF;
    int*   tabi  = (int*)(sm + TAB_OFF);
    int*   basei = (int*)(sm + BASE_OFF);
    float* ssc   = (float*)(sm + SC_OFF);
    float* ssh   = (float*)(sm + SH_OFF);
    const uint32_t sbase = smem_u32(sm);

    const int tid = threadIdx.x;
    const int w = tid >> 5, lane = tid & 31;
    const int gi = lane >> 2, ti = lane & 3;
    const int mt = blockIdx.x;
    const int r0 = (w >> 1) * 16;
    const int c0 = (w & 1) * 128;

    for (int k = tid; k < 1152; k += 512) {
        int ci = k / 9, r = k - ci * 9;
        tabi[k] = ci * 361 + (r / 3) * 19 + (r % 3);
    }
    if (tid < 128) {
        int mg = mt * 128 + tid;
        int b = mg / 81, p = mg - b * 81;
        basei[tid] = b * 46208 + (p / 9) * 38 + (p % 9) * 2;
    }
    if (tid < 256) {
        float inv = g[tid] / sqrtf(v[tid] + BN_EPSF);
        ssc[tid] = inv;
        ssh[tid] = cb[tid] * inv + (bb[tid] - m[tid] * inv);
    }
    __syncthreads();

    float d[16][4];
#pragma unroll
    for (int s = 0; s < 16; ++s)
#pragma unroll
        for (int q = 0; q < 4; ++q) d[s][q] = 0.0f;

    const int am = tid >> 2;
    const int akb = (tid & 3) * 16;
    const int awb = akb >> 1;

    float fr[16];

    {
#pragma unroll
        for (int j = 0; j < 8; ++j) {
            int idx = tid + (j << 9);
            int hl = idx >> 11, n = (idx >> 3) & 255, seg = idx & 7;
            const uint32_t* gsrc = (hl ? g_wbl : g_wbh) + n * 576 + seg * 4;
            uint32_t saddr = sbase + (B_OFF + hl * B_HL_STRIDE + n * 36 + seg * 4) * 4;
            cp_async16(saddr, gsrc);
        }
        CP_COMMIT();
        const float* src = g_h1 + basei[am];
        const int* tp = tabi + akb;
#pragma unroll
        for (int j = 0; j < 16; ++j) fr[j] = src[tp[j]];
    }

    for (int ch = 0; ch < 18; ++ch) {
        const int buf = ch & 1;
        {
            uint32_t* dH = sAh + am * 36 + awb;
            uint32_t* dL = sAl + am * 36 + awb;
#pragma unroll
            for (int j = 0; j < 8; ++j) {
                uint32_t lo;
                uint32_t hi = bfsplit_pack_hi(fr[2 * j], fr[2 * j + 1], lo);
                dH[j] = hi;
                dL[j] = lo;
            }
        }
        if (ch < 17) {
            const int kp0n = (ch + 1) * 32;
#pragma unroll
            for (int j = 0; j < 8; ++j) {
                int idx = tid + (j << 9);
                int hl = idx >> 11, n = (idx >> 3) & 255, seg = idx & 7;
                const uint32_t* gsrc = (hl ? g_wbl : g_wbh) + n * 576 + kp0n + seg * 4;
                uint32_t saddr = sbase + (B_OFF + (buf ^ 1) * B_BUF_STRIDE + hl * B_HL_STRIDE + n * 36 + seg * 4) * 4;
                cp_async16(saddr, gsrc);
            }
            CP_COMMIT();
            const float* src = g_h1 + basei[am];
            const int* tp = tabi + (ch + 1) * 64 + akb;
#pragma unroll
            for (int j = 0; j < 16; ++j) fr[j] = src[tp[j]];
            CP_WAIT1();
        } else {
            CP_WAIT0();
        }
        __syncthreads();

        const uint32_t* sBh = sm + B_OFF + buf * B_BUF_STRIDE;
        const uint32_t* sBl = sBh + B_HL_STRIDE;
        const uint32_t* AhR = sAh + (r0 + gi) * 36;
        const uint32_t* AlR = sAl + (r0 + gi) * 36;
#pragma unroll
        for (int s16 = 0; s16 < 4; ++s16) {
            const int kw = s16 * 8;
            uint32_t ah0 = AhR[kw + ti],          ah1 = AhR[8 * 36 + kw + ti];
            uint32_t ah2 = AhR[kw + ti + 4],      ah3 = AhR[8 * 36 + kw + ti + 4];
            uint32_t al0 = AlR[kw + ti],          al1 = AlR[8 * 36 + kw + ti];
            uint32_t al2 = AlR[kw + ti + 4],      al3 = AlR[8 * 36 + kw + ti + 4];
#pragma unroll
            for (int s = 0; s < 16; ++s) {
                const int br = (c0 + s * 8 + gi) * 36 + kw;
                uint32_t bh0 = sBh[br + ti], bh1 = sBh[br + ti + 4];
                uint32_t bl0 = sBl[br + ti], bl1 = sBl[br + ti + 4];
                asm volatile(
                    "mma.sync.aligned.m16n8k16.row.col.f32.bf16.bf16.f32 "
                    "{%0,%1,%2,%3}, {%4,%5,%6,%7}, {%8,%9}, {%0,%1,%2,%3};"
                    : "+f"(d[s][0]), "+f"(d[s][1]), "+f"(d[s][2]), "+f"(d[s][3])
                    : "r"(ah0), "r"(ah1), "r"(ah2), "r"(ah3), "r"(bh0), "r"(bh1));
                asm volatile(
                    "mma.sync.aligned.m16n8k16.row.col.f32.bf16.bf16.f32 "
                    "{%0,%1,%2,%3}, {%4,%5,%6,%7}, {%8,%9}, {%0,%1,%2,%3};"
                    : "+f"(d[s][0]), "+f"(d[s][1]), "+f"(d[s][2]), "+f"(d[s][3])
                    : "r"(ah0), "r"(ah1), "r"(ah2), "r"(ah3), "r"(bl0), "r"(bl1));
                asm volatile(
                    "mma.sync.aligned.m16n8k16.row.col.f32.bf16.bf16.f32 "
                    "{%0,%1,%2,%3}, {%4,%5,%6,%7}, {%8,%9}, {%0,%1,%2,%3};"
                    : "+f"(d[s][0]), "+f"(d[s][1]), "+f"(d[s][2]), "+f"(d[s][3])
                    : "r"(al0), "r"(al1), "r"(al2), "r"(al3), "r"(bh0), "r"(bh1));
            }
        }
        __syncthreads();
    }

    const int mrow0 = mt * 128 + r0 + gi;
#pragma unroll
    for (int s = 0; s < 16; ++s) {
        int cl = c0 + s * 8 + 2 * ti;
        float sc0 = ssc[cl], sc1 = ssc[cl + 1];
        float sh0 = ssh[cl], sh1 = ssh[cl + 1];
        float v0 = d[s][0] * sc0 + sh0; v0 = v0 > 0.0f ? v0 : 0.0f;
        float v1 = d[s][1] * sc1 + sh1; v1 = v1 > 0.0f ? v1 : 0.0f;
        float v2 = d[s][2] * sc0 + sh0; v2 = v2 > 0.0f ? v2 : 0.0f;
        float v3 = d[s][3] * sc1 + sh1; v3 = v3 > 0.0f ? v3 : 0.0f;
        *(float2*)(g_h2 + (size_t)mrow0 * 256 + cl)       = make_float2(v0, v1);
        *(float2*)(g_h2 + (size_t)(mrow0 + 8) * 256 + cl) = make_float2(v2, v3);
    }
}

// ---------------- conv3 (depthwise 9x9) + squash -> g_u ----------------
__global__ void conv3s_kernel(const float* __restrict__ w3, const float* __restrict__ b3)
{
    int b = blockIdx.x, c = threadIdx.x;
    const float* h2b = g_h2 + b * 81 * 256;
    float acc = 0.0f;
#pragma unroll
    for (int p = 0; p < 81; ++p)
        acc = fmaf(h2b[p * 256 + c], w3[c * 81 + p], acc);
    acc += b3[c];

    float sq = acc * acc;
    sq += __shfl_xor_sync(0xffffffffu, sq, 4);
    sq += __shfl_xor_sync(0xffffffffu, sq, 2);
    sq += __shfl_xor_sync(0xffffffffu, sq, 1);
    float nrm = sqrtf(sq);
    float t1 = 1.0f - 1.0f / (exp_matched(nrm) + EPSF);
    g_u[b * 256 + c] = t1 * (acc / (nrm + EPSF));
}

// ---------------- U_hat GEMM: grid (32 i, 8 batch-chunks of 64), 256 threads ----------------
template<int NH, int DH>
__global__ void __launch_bounds__(256) uhat_kernel(const float* __restrict__ W)
{
    constexpr int NHDH = NH * DH;
    __shared__ float sW[8 * NHDH];     // [j][k*DH+l]
    __shared__ float sUb[64 * 8];      // [bb][j]
    const int i = blockIdx.x;
    const int b0 = blockIdx.y * 64;
    const int tid = threadIdx.x;

    for (int idx = tid; idx < 8 * NHDH; idx += 256) {
        int k = idx / (8 * DH);
        int r = idx % (8 * DH);
        int j = r / DH, l = r % DH;
        sW[j * NHDH + k * DH + l] = W[i * NH * 8 * DH + idx];
    }
    for (int idx = tid; idx < 512; idx += 256) {
        int bb = idx >> 3, j = idx & 7;
        sUb[idx] = g_u[(b0 + bb) * 256 + i * 8 + j];
    }
    __syncthreads();

    if (tid < NHDH) {
        float wr[8];
#pragma unroll
        for (int j = 0; j < 8; ++j) wr[j] = sW[j * NHDH + tid];
        float* dst = g_uhat + (size_t)b0 * (32 * NHDH) + i * NHDH + tid;
#pragma unroll 4
        for (int bb = 0; bb < 64; ++bb) {
            const float* u = sUb + bb * 8;
            float a = 0.0f;
#pragma unroll
            for (int j = 0; j < 8; ++j) a = fmaf(u[j], wr[j], a);
            dst[(size_t)bb * (32 * NHDH)] = a;
        }
    }
}

// ---------------- attention + squash: one block per batch ----------------
template<int NH, int DH, bool FINAL>
__global__ void __launch_bounds__(256) attn_kernel(float* __restrict__ outp)
{
    constexpr int NHDH = NH * DH;
    constexpr int NL = 32;
    __shared__ float sUhat[NL * NHDH];
    __shared__ float sS[NHDH];
    __shared__ float sA[NL * NH];
    const int b = blockIdx.x, tid = threadIdx.x;

    // fused load + S accumulation: thread t owns column t; loads coalesced across t
    if (tid < NHDH) {
        const float* src = g_uhat + (size_t)b * (NL * NHDH) + tid;
        float ssum = 0.0f;
#pragma unroll
        for (int i = 0; i < NL; ++i) {
            float vv = src[i * NHDH];
            sUhat[i * NHDH + tid] = vv;
            ssum += vv;
        }
        sS[tid] = ssum;
    }
    __syncthreads();

    for (int idx = tid; idx < NL * NH; idx += 256) {
        int i = idx / NH, k = idx % NH;
        float a = 0.0f;
#pragma unroll
        for (int l = 0; l < DH; ++l) a = fmaf(sS[k * DH + l], sUhat[i * NHDH + k * DH + l], a);
        sA[idx] = a * INV_ATTN;
    }
    __syncthreads();

    {
        int wid = tid >> 5, lane = tid & 31;
#pragma unroll
        for (int q = 0; q < 4; ++q) {
            int i = wid * 4 + q;
            float val = (lane < NH) ? sA[i * NH + lane] : -1e30f;
            float mx = val;
#pragma unroll
            for (int o = 16; o; o >>= 1) mx = fmaxf(mx, __shfl_xor_sync(0xffffffffu, mx, o));
            float e = (lane < NH) ? expf(val - mx) : 0.0f;
            float sum = e;
#pragma unroll
            for (int o = 16; o; o >>= 1) sum += __shfl_xor_sync(0xffffffffu, sum, o);
            if (lane < NH) sA[i * NH + lane] = e / sum;
        }
    }
    __syncthreads();

    if (tid < NHDH) {
        int k = tid / DH;
        float acc = 0.0f;
#pragma unroll
        for (int i = 0; i < NL; ++i) acc = fmaf(sA[i * NH + k], sUhat[i * NHDH + tid], acc);
        float sq = acc * acc;
#pragma unroll
        for (int o = DH / 2; o; o >>= 1) sq += __shfl_xor_sync(0xffffffffu, sq, o);
        float nrm = sqrtf(sq);
        float t1 = 1.0f - 1.0f / (exp_matched(nrm) + EPSF);
        float val = t1 * (acc / (nrm + EPSF));
        if (FINAL) outp[(size_t)b * NHDH + tid] = val;
        else       g_u[(size_t)b * 256 + tid] = val;
    }
}

// ---------------- launch ----------------
extern "C" void kernel_launch(void* const* d_in, const int* in_sizes, int n_in,
                              void* d_out, int out_size)
{
    const float* x       = (const float*)d_in[0];
    const float* conv1_w = (const float*)d_in[1];
    const float* conv1_b = (const float*)d_in[2];
    const float* bn1_g   = (const float*)d_in[3];
    const float* bn1_b   = (const float*)d_in[4];
    const float* bn1_m   = (const float*)d_in[5];
    const float* bn1_v   = (const float*)d_in[6];
    const float* conv2_w = (const float*)d_in[7];
    const float* conv2_b = (const float*)d_in[8];
    const float* bn2_g   = (const float*)d_in[9];
    const float* bn2_b   = (const float*)d_in[10];
    const float* bn2_m   = (const float*)d_in[11];
    const float* bn2_v   = (const float*)d_in[12];
    const float* conv3_w = (const float*)d_in[13];
    const float* conv3_b = (const float*)d_in[14];
    const float* W1      = (const float*)d_in[15];
    const float* W2      = (const float*)d_in[16];
    const float* W3      = (const float*)d_in[17];
    float* out = (float*)d_out;

    cudaFuncSetAttribute(conv2_mma_kernel, cudaFuncAttributeMaxDynamicSharedMemorySize,
                         C2_SMEM_WORDS * (int)sizeof(uint32_t));

    conv1_kernel<<<dim3(NB, 4), 384>>>(x, conv1_w, conv1_b, bn1_g, bn1_b, bn1_m, bn1_v);
    wtrans_kernel<<<576, 256>>>(conv2_w);
    conv2_mma_kernel<<<324, 512, C2_SMEM_WORDS * sizeof(uint32_t)>>>(
        conv2_b, bn2_g, bn2_b, bn2_m, bn2_v);
    conv3s_kernel<<<NB, 256>>>(conv3_w, conv3_b);

    uhat_kernel<32, 8><<<dim3(32, 8), 256>>>(W1);
    attn_kernel<32, 8, false><<<NB, 256>>>(nullptr);
    uhat_kernel<32, 8><<<dim3(32, 8), 256>>>(W2);
    attn_kernel<32, 8, false><<<NB, 256>>>(nullptr);
    uhat_kernel<10, 16><<<dim3(32, 8), 256>>>(W3);
    attn_kernel<10, 16, true><<<NB, 256>>>(out);
}

// round 16
// speedup vs baseline: 1.3760x; 1.0745x over previous
#include <cuda_runtime.h>
#include <cuda_bf16.h>
#include <math.h>
#include <stdint.h>

#define NB 512
#define EPSF 1e-20f
#define BN_EPSF 1e-5f
#define INV_ATTN 0.35355339059327373f   // 1/sqrt(8)

__device__ __forceinline__ float exp_matched(float n) {
    if (n < 0.05f) {
        float p = fmaf(n, 1.0f / 120.0f, 1.0f / 24.0f);
        p = fmaf(p, n, 1.0f / 6.0f);
        p = fmaf(p, n, 0.5f);
        return 1.0f + fmaf(n * n, p, n);
    }
    return expf(n);
}

__device__ __forceinline__ uint32_t bfsplit_pack_hi(float x0, float x1, uint32_t& lo) {
    __nv_bfloat16 h0 = __float2bfloat16(x0), h1 = __float2bfloat16(x1);
    __nv_bfloat16 l0 = __float2bfloat16(x0 - __bfloat162float(h0));
    __nv_bfloat16 l1 = __float2bfloat16(x1 - __bfloat162float(h1));
    lo = (uint32_t)__bfloat16_as_ushort(l0) | ((uint32_t)__bfloat16_as_ushort(l1) << 16);
    return (uint32_t)__bfloat16_as_ushort(h0) | ((uint32_t)__bfloat16_as_ushort(h1) << 16);
}

__device__ __forceinline__ uint32_t smem_u32(const void* p) {
    uint32_t a;
    asm("{ .reg .u64 t; cvta.to.shared.u64 t, %1; cvt.u32.u64 %0, t; }" : "=r"(a) : "l"(p));
    return a;
}
__device__ __forceinline__ void cp_async16(uint32_t saddr, const void* gptr) {
    asm volatile("cp.async.cg.shared.global [%0], [%1], 16;" :: "r"(saddr), "l"(gptr));
}
#define CP_COMMIT() asm volatile("cp.async.commit_group;" ::: "memory")
#define CP_WAIT0()  asm volatile("cp.async.wait_group 0;" ::: "memory")

// ---------------- scratch (device globals; device-code use only) ----------------
__device__ float g_h1[NB * 128 * 19 * 19];     // conv1 out
__device__ float g_h2[NB * 81 * 256];          // conv2 out, [b*81+p][co]
__device__ uint32_t g_wbh[256 * 576];
__device__ uint32_t g_wbl[256 * 576];
__device__ float g_u[NB * 256];
__device__ float g_uhat[NB * 8192];

// ---------------- conv1 + bn + relu : grid (batch, 4 co-groups) ----------------
__global__ void __launch_bounds__(384) conv1_kernel(
    const float* __restrict__ x, const float* __restrict__ w, const float* __restrict__ cb,
    const float* __restrict__ g, const float* __restrict__ bb,
    const float* __restrict__ m, const float* __restrict__ v)
{
    int b = blockIdx.x, co0 = blockIdx.y * 32, tid = threadIdx.x;
    __shared__ float s_in[39 * 39];
    __shared__ float s_w[32 * 9];
    __shared__ float s_sc[32], s_sh[32];
    const float* xb = x + b * 1521;
    for (int i = tid; i < 1521; i += 384) s_in[i] = xb[i];
    if (tid < 288) s_w[tid] = w[co0 * 9 + tid];
    if (tid < 32) {
        int co = co0 + tid;
        float inv = g[co] / sqrtf(v[co] + BN_EPSF);
        s_sc[tid] = inv;
        s_sh[tid] = cb[co] * inv + (bb[co] - m[co] * inv);
    }
    __syncthreads();
    if (tid < 361) {
        int oy = tid / 19, ox = tid % 19;
        float r[9];
#pragma unroll
        for (int kh = 0; kh < 3; ++kh)
#pragma unroll
            for (int kw = 0; kw < 3; ++kw)
                r[kh * 3 + kw] = s_in[(oy * 2 + kh) * 39 + ox * 2 + kw];
        float* outb = g_h1 + b * 128 * 361 + co0 * 361 + tid;
#pragma unroll 4
        for (int cl = 0; cl < 32; ++cl) {
            float acc = 0.0f;
#pragma unroll
            for (int k = 0; k < 9; ++k) acc = fmaf(r[k], s_w[cl * 9 + k], acc);
            float y = acc * s_sc[cl] + s_sh[cl];
            outb[cl * 361] = y > 0.0f ? y : 0.0f;
        }
    }
}

// ---------------- conv2 weight prep ----------------
__global__ void wtrans_kernel(const float* __restrict__ w2)
{
    int widx = blockIdx.x * 256 + threadIdx.x;
    int n = widx / 576, kp = widx % 576;
    uint32_t lo;
    uint32_t hi = bfsplit_pack_hi(w2[n * 1152 + 2 * kp], w2[n * 1152 + 2 * kp + 1], lo);
    g_wbh[widx] = hi;
    g_wbl[widx] = lo;
}

// ---------------- conv2 implicit GEMM: A+B double-buffered, 1 sync/chunk,
//                  B cp.async issued AFTER the barrier (overlaps MMA, race-free) ----------------
#define A_OFF 0
#define A_BUF_STRIDE 9216
#define AL_REL 4608
#define B_OFF 18432
#define B_BUF_STRIDE 18432
#define B_HL_STRIDE 9216
#define TAB_OFF 55296
#define BASE_OFF 56448
#define SC_OFF 56576
#define SH_OFF 56832
#define C2_SMEM_WORDS 57088   // 228,352 bytes

__global__ void __launch_bounds__(512, 1) conv2_mma_kernel(
    const float* __restrict__ cb,
    const float* __restrict__ g, const float* __restrict__ bb,
    const float* __restrict__ m, const float* __restrict__ v)
{
    extern __shared__ uint32_t sm[];
    int*   tabi  = (int*)(sm + TAB_OFF);
    int*   basei = (int*)(sm + BASE_OFF);
    float* ssc   = (float*)(sm + SC_OFF);
    float* ssh   = (float*)(sm + SH_OFF);
    const uint32_t sbase = smem_u32(sm);

    const int tid = threadIdx.x;
    const int w = tid >> 5, lane = tid & 31;
    const int gi = lane >> 2, ti = lane & 3;
    const int mt = blockIdx.x;
    const int r0 = (w >> 1) * 16;
    const int c0 = (w & 1) * 128;

    for (int k = tid; k < 1152; k += 512) {
        int ci = k / 9, r = k - ci * 9;
        tabi[k] = ci * 361 + (r / 3) * 19 + (r % 3);
    }
    if (tid < 128) {
        int mg = mt * 128 + tid;
        int b = mg / 81, p = mg - b * 81;
        basei[tid] = b * 46208 + (p / 9) * 38 + (p % 9) * 2;
    }
    if (tid < 256) {
        float inv = g[tid] / sqrtf(v[tid] + BN_EPSF);
        ssc[tid] = inv;
        ssh[tid] = cb[tid] * inv + (bb[tid] - m[tid] * inv);
    }
    __syncthreads();

    float d[16][4];
#pragma unroll
    for (int s = 0; s < 16; ++s)
#pragma unroll
        for (int q = 0; q < 4; ++q) d[s][q] = 0.0f;

    const int am = tid >> 2;
    const int akb = (tid & 3) * 16;
    const int awb = akb >> 1;

    float fr[16];

    // ---- prologue: B(0) cp.async + A(0) gather ----
    {
#pragma unroll
        for (int j = 0; j < 8; ++j) {
            int idx = tid + (j << 9);
            int hl = idx >> 11, n = (idx >> 3) & 255, seg = idx & 7;
            const uint32_t* gsrc = (hl ? g_wbl : g_wbh) + n * 576 + seg * 4;
            uint32_t saddr = sbase + (B_OFF + hl * B_HL_STRIDE + n * 36 + seg * 4) * 4;
            cp_async16(saddr, gsrc);
        }
        CP_COMMIT();
        const float* src = g_h1 + basei[am];
        const int* tp = tabi + akb;
#pragma unroll
        for (int j = 0; j < 16; ++j) fr[j] = src[tp[j]];
    }

    for (int ch = 0; ch < 18; ++ch) {
        const int buf = ch & 1;
        // ---- cvt + STS A(ch) into Abuf[buf] (MMA(ch-1) read Abuf[buf^1]; MMA(ch-2)
        //      readers of Abuf[buf] all passed sync(ch-1) — barrier-ordered, safe) ----
        {
            uint32_t* dH = sm + A_OFF + buf * A_BUF_STRIDE + am * 36 + awb;
            uint32_t* dL = dH + AL_REL;
#pragma unroll
            for (int j = 0; j < 8; ++j) {
                uint32_t lo;
                uint32_t hi = bfsplit_pack_hi(fr[2 * j], fr[2 * j + 1], lo);
                dH[j] = hi;
                dL[j] = lo;
            }
        }
        // ---- prefetch A(ch+1) gather into regs (completes under MMA(ch)) ----
        if (ch < 17) {
            const float* src = g_h1 + basei[am];
            const int* tp = tabi + (ch + 1) * 64 + akb;
#pragma unroll
            for (int j = 0; j < 16; ++j) fr[j] = src[tp[j]];
        }
        CP_WAIT0();          // B(ch) fully landed in Bbuf[buf]
        __syncthreads();     // publishes A(ch) + B(ch); orders MMA(ch-1) before B issue below

        // ---- issue cp.async B(ch+1) into Bbuf[buf^1]; overlaps MMA(ch).
        //      Safe: all MMA(ch-1) reads of Bbuf[buf^1] precede sync(ch) above. ----
        if (ch < 17) {
            const int kp0n = (ch + 1) * 32;
#pragma unroll
            for (int j = 0; j < 8; ++j) {
                int idx = tid + (j << 9);
                int hl = idx >> 11, n = (idx >> 3) & 255, seg = idx & 7;
                const uint32_t* gsrc = (hl ? g_wbl : g_wbh) + n * 576 + kp0n + seg * 4;
                uint32_t saddr = sbase + (B_OFF + (buf ^ 1) * B_BUF_STRIDE + hl * B_HL_STRIDE + n * 36 + seg * 4) * 4;
                cp_async16(saddr, gsrc);
            }
            CP_COMMIT();
        }

        // ---- MMA(ch) ----
        const uint32_t* sBh = sm + B_OFF + buf * B_BUF_STRIDE;
        const uint32_t* sBl = sBh + B_HL_STRIDE;
        const uint32_t* AhR = sm + A_OFF + buf * A_BUF_STRIDE + (r0 + gi) * 36;
        const uint32_t* AlR = AhR + AL_REL;
#pragma unroll
        for (int s16 = 0; s16 < 4; ++s16) {
            const int kw = s16 * 8;
            uint32_t ah0 = AhR[kw + ti],          ah1 = AhR[8 * 36 + kw + ti];
            uint32_t ah2 = AhR[kw + ti + 4],      ah3 = AhR[8 * 36 + kw + ti + 4];
            uint32_t al0 = AlR[kw + ti],          al1 = AlR[8 * 36 + kw + ti];
            uint32_t al2 = AlR[kw + ti + 4],      al3 = AlR[8 * 36 + kw + ti + 4];
#pragma unroll
            for (int s = 0; s < 16; ++s) {
                const int br = (c0 + s * 8 + gi) * 36 + kw;
                uint32_t bh0 = sBh[br + ti], bh1 = sBh[br + ti + 4];
                uint32_t bl0 = sBl[br + ti], bl1 = sBl[br + ti + 4];
                asm volatile(
                    "mma.sync.aligned.m16n8k16.row.col.f32.bf16.bf16.f32 "
                    "{%0,%1,%2,%3}, {%4,%5,%6,%7}, {%8,%9}, {%0,%1,%2,%3};"
                    : "+f"(d[s][0]), "+f"(d[s][1]), "+f"(d[s][2]), "+f"(d[s][3])
                    : "r"(ah0), "r"(ah1), "r"(ah2), "r"(ah3), "r"(bh0), "r"(bh1));
                asm volatile(
                    "mma.sync.aligned.m16n8k16.row.col.f32.bf16.bf16.f32 "
                    "{%0,%1,%2,%3}, {%4,%5,%6,%7}, {%8,%9}, {%0,%1,%2,%3};"
                    : "+f"(d[s][0]), "+f"(d[s][1]), "+f"(d[s][2]), "+f"(d[s][3])
                    : "r"(ah0), "r"(ah1), "r"(ah2), "r"(ah3), "r"(bl0), "r"(bl1));
                asm volatile(
                    "mma.sync.aligned.m16n8k16.row.col.f32.bf16.bf16.f32 "
                    "{%0,%1,%2,%3}, {%4,%5,%6,%7}, {%8,%9}, {%0,%1,%2,%3};"
                    : "+f"(d[s][0]), "+f"(d[s][1]), "+f"(d[s][2]), "+f"(d[s][3])
                    : "r"(al0), "r"(al1), "r"(al2), "r"(al3), "r"(bh0), "r"(bh1));
            }
        }
    }

    const int mrow0 = mt * 128 + r0 + gi;
#pragma unroll
    for (int s = 0; s < 16; ++s) {
        int cl = c0 + s * 8 + 2 * ti;
        float sc0 = ssc[cl], sc1 = ssc[cl + 1];
        float sh0 = ssh[cl], sh1 = ssh[cl + 1];
        float v0 = d[s][0] * sc0 + sh0; v0 = v0 > 0.0f ? v0 : 0.0f;
        float v1 = d[s][1] * sc1 + sh1; v1 = v1 > 0.0f ? v1 : 0.0f;
        float v2 = d[s][2] * sc0 + sh0; v2 = v2 > 0.0f ? v2 : 0.0f;
        float v3 = d[s][3] * sc1 + sh1; v3 = v3 > 0.0f ? v3 : 0.0f;
        *(float2*)(g_h2 + (size_t)mrow0 * 256 + cl)       = make_float2(v0, v1);
        *(float2*)(g_h2 + (size_t)(mrow0 + 8) * 256 + cl) = make_float2(v2, v3);
    }
}

// ---------------- conv3 (depthwise 9x9) + squash -> g_u ----------------
__global__ void conv3s_kernel(const float* __restrict__ w3, const float* __restrict__ b3)
{
    int b = blockIdx.x, c = threadIdx.x;
    const float* h2b = g_h2 + b * 81 * 256;
    float acc = 0.0f;
#pragma unroll
    for (int p = 0; p < 81; ++p)
        acc = fmaf(h2b[p * 256 + c], w3[c * 81 + p], acc);
    acc += b3[c];

    float sq = acc * acc;
    sq += __shfl_xor_sync(0xffffffffu, sq, 4);
    sq += __shfl_xor_sync(0xffffffffu, sq, 2);
    sq += __shfl_xor_sync(0xffffffffu, sq, 1);
    float nrm = sqrtf(sq);
    float t1 = 1.0f - 1.0f / (exp_matched(nrm) + EPSF);
    g_u[b * 256 + c] = t1 * (acc / (nrm + EPSF));
}

// ---------------- U_hat GEMM ----------------
template<int NH, int DH>
__global__ void __launch_bounds__(256) uhat_kernel(const float* __restrict__ W)
{
    constexpr int NHDH = NH * DH;
    __shared__ float sW[8 * NHDH];
    __shared__ float sUb[64 * 8];
    const int i = blockIdx.x;
    const int b0 = blockIdx.y * 64;
    const int tid = threadIdx.x;

    for (int idx = tid; idx < 8 * NHDH; idx += 256) {
        int k = idx / (8 * DH);
        int r = idx % (8 * DH);
        int j = r / DH, l = r % DH;
        sW[j * NHDH + k * DH + l] = W[i * NH * 8 * DH + idx];
    }
    for (int idx = tid; idx < 512; idx += 256) {
        int bb = idx >> 3, j = idx & 7;
        sUb[idx] = g_u[(b0 + bb) * 256 + i * 8 + j];
    }
    __syncthreads();

    if (tid < NHDH) {
        float wr[8];
#pragma unroll
        for (int j = 0; j < 8; ++j) wr[j] = sW[j * NHDH + tid];
        float* dst = g_uhat + (size_t)b0 * (32 * NHDH) + i * NHDH + tid;
#pragma unroll 4
        for (int bb = 0; bb < 64; ++bb) {
            const float* u = sUb + bb * 8;
            float a = 0.0f;
#pragma unroll
            for (int j = 0; j < 8; ++j) a = fmaf(u[j], wr[j], a);
            dst[(size_t)bb * (32 * NHDH)] = a;
        }
    }
}

// ---------------- attention + squash ----------------
template<int NH, int DH, bool FINAL>
__global__ void __launch_bounds__(256) attn_kernel(float* __restrict__ outp)
{
    constexpr int NHDH = NH * DH;
    constexpr int NL = 32;
    __shared__ float sUhat[NL * NHDH];
    __shared__ float sS[NHDH];
    __shared__ float sA[NL * NH];
    const int b = blockIdx.x, tid = threadIdx.x;

    if (tid < NHDH) {
        const float* src = g_uhat + (size_t)b * (NL * NHDH) + tid;
        float ssum = 0.0f;
#pragma unroll
        for (int i = 0; i < NL; ++i) {
            float vv = src[i * NHDH];
            sUhat[i * NHDH + tid] = vv;
            ssum += vv;
        }
        sS[tid] = ssum;
    }
    __syncthreads();

    for (int idx = tid; idx < NL * NH; idx += 256) {
        int i = idx / NH, k = idx % NH;
        float a = 0.0f;
#pragma unroll
        for (int l = 0; l < DH; ++l) a = fmaf(sS[k * DH + l], sUhat[i * NHDH + k * DH + l], a);
        sA[idx] = a * INV_ATTN;
    }
    __syncthreads();

    {
        int wid = tid >> 5, lane = tid & 31;
#pragma unroll
        for (int q = 0; q < 4; ++q) {
            int i = wid * 4 + q;
            float val = (lane < NH) ? sA[i * NH + lane] : -1e30f;
            float mx = val;
#pragma unroll
            for (int o = 16; o; o >>= 1) mx = fmaxf(mx, __shfl_xor_sync(0xffffffffu, mx, o));
            float e = (lane < NH) ? expf(val - mx) : 0.0f;
            float sum = e;
#pragma unroll
            for (int o = 16; o; o >>= 1) sum += __shfl_xor_sync(0xffffffffu, sum, o);
            if (lane < NH) sA[i * NH + lane] = e / sum;
        }
    }
    __syncthreads();

    if (tid < NHDH) {
        int k = tid / DH;
        float acc = 0.0f;
#pragma unroll
        for (int i = 0; i < NL; ++i) acc = fmaf(sA[i * NH + k], sUhat[i * NHDH + tid], acc);
        float sq = acc * acc;
#pragma unroll
        for (int o = DH / 2; o; o >>= 1) sq += __shfl_xor_sync(0xffffffffu, sq, o);
        float nrm = sqrtf(sq);
        float t1 = 1.0f - 1.0f / (exp_matched(nrm) + EPSF);
        float val = t1 * (acc / (nrm + EPSF));
        if (FINAL) outp[(size_t)b * NHDH + tid] = val;
        else       g_u[(size_t)b * 256 + tid] = val;
    }
}

// ---------------- launch ----------------
extern "C" void kernel_launch(void* const* d_in, const int* in_sizes, int n_in,
                              void* d_out, int out_size)
{
    const float* x       = (const float*)d_in[0];
    const float* conv1_w = (const float*)d_in[1];
    const float* conv1_b = (const float*)d_in[2];
    const float* bn1_g   = (const float*)d_in[3];
    const float* bn1_b   = (const float*)d_in[4];
    const float* bn1_m   = (const float*)d_in[5];
    const float* bn1_v   = (const float*)d_in[6];
    const float* conv2_w = (const float*)d_in[7];
    const float* conv2_b = (const float*)d_in[8];
    const float* bn2_g   = (const float*)d_in[9];
    const float* bn2_b   = (const float*)d_in[10];
    const float* bn2_m   = (const float*)d_in[11];
    const float* bn2_v   = (const float*)d_in[12];
    const float* conv3_w = (const float*)d_in[13];
    const float* conv3_b = (const float*)d_in[14];
    const float* W1      = (const float*)d_in[15];
    const float* W2      = (const float*)d_in[16];
    const float* W3      = (const float*)d_in[17];
    float* out = (float*)d_out;

    cudaFuncSetAttribute(conv2_mma_kernel, cudaFuncAttributeMaxDynamicSharedMemorySize,
                         C2_SMEM_WORDS * (int)sizeof(uint32_t));

    conv1_kernel<<<dim3(NB, 4), 384>>>(x, conv1_w, conv1_b, bn1_g, bn1_b, bn1_m, bn1_v);
    wtrans_kernel<<<576, 256>>>(conv2_w);
    conv2_mma_kernel<<<324, 512, C2_SMEM_WORDS * sizeof(uint32_t)>>>(
        conv2_b, bn2_g, bn2_b, bn2_m, bn2_v);
    conv3s_kernel<<<NB, 256>>>(conv3_w, conv3_b);

    uhat_kernel<32, 8><<<dim3(32, 8), 256>>>(W1);
    attn_kernel<32, 8, false><<<NB, 256>>>(nullptr);
    uhat_kernel<32, 8><<<dim3(32, 8), 256>>>(W2);
    attn_kernel<32, 8, false><<<NB, 256>>>(nullptr);
    uhat_kernel<10, 16><<<dim3(32, 8), 256>>>(W3);
    attn_kernel<10, 16, true><<<NB, 256>>>(out);
}

// round 17
// speedup vs baseline: 1.5637x; 1.1364x over previous
#include <cuda_runtime.h>
#include <cuda_bf16.h>
#include <math.h>
#include <stdint.h>

#define NB 512
#define EPSF 1e-20f
#define BN_EPSF 1e-5f
#define INV_ATTN 0.35355339059327373f   // 1/sqrt(8)

__device__ __forceinline__ float exp_matched(float n) {
    if (n < 0.05f) {
        float p = fmaf(n, 1.0f / 120.0f, 1.0f / 24.0f);
        p = fmaf(p, n, 1.0f / 6.0f);
        p = fmaf(p, n, 0.5f);
        return 1.0f + fmaf(n * n, p, n);
    }
    return expf(n);
}

__device__ __forceinline__ uint32_t bfsplit_pack_hi(float x0, float x1, uint32_t& lo) {
    __nv_bfloat16 h0 = __float2bfloat16(x0), h1 = __float2bfloat16(x1);
    __nv_bfloat16 l0 = __float2bfloat16(x0 - __bfloat162float(h0));
    __nv_bfloat16 l1 = __float2bfloat16(x1 - __bfloat162float(h1));
    lo = (uint32_t)__bfloat16_as_ushort(l0) | ((uint32_t)__bfloat16_as_ushort(l1) << 16);
    return (uint32_t)__bfloat16_as_ushort(h0) | ((uint32_t)__bfloat16_as_ushort(h1) << 16);
}

__device__ __forceinline__ uint32_t smem_u32(const void* p) {
    uint32_t a;
    asm("{ .reg .u64 t; cvta.to.shared.u64 t, %1; cvt.u32.u64 %0, t; }" : "=r"(a) : "l"(p));
    return a;
}
__device__ __forceinline__ void cp_async16(uint32_t saddr, const void* gptr) {
    asm volatile("cp.async.cg.shared.global [%0], [%1], 16;" :: "r"(saddr), "l"(gptr));
}
#define CP_COMMIT() asm volatile("cp.async.commit_group;" ::: "memory")
#define CP_WAIT0()  asm volatile("cp.async.wait_group 0;" ::: "memory")

// ---------------- scratch ----------------
__device__ float g_h1[NB * 128 * 19 * 19];
__device__ float g_h2[NB * 81 * 256];
__device__ uint32_t g_wbh[256 * 576];
__device__ uint32_t g_wbl[256 * 576];
__device__ float g_u[NB * 256];
__device__ float g_uhat[NB * 8192];

// ---------------- conv1 + bn + relu : grid (batch, 4 co-groups) ----------------
__global__ void __launch_bounds__(384) conv1_kernel(
    const float* __restrict__ x, const float* __restrict__ w, const float* __restrict__ cb,
    const float* __restrict__ g, const float* __restrict__ bb,
    const float* __restrict__ m, const float* __restrict__ v)
{
    int b = blockIdx.x, co0 = blockIdx.y * 32, tid = threadIdx.x;
    __shared__ float s_in[39 * 39];
    __shared__ float s_w[32 * 9];
    __shared__ float s_sc[32], s_sh[32];
    const float* xb = x + b * 1521;
    for (int i = tid; i < 1521; i += 384) s_in[i] = xb[i];
    if (tid < 288) s_w[tid] = w[co0 * 9 + tid];
    if (tid < 32) {
        int co = co0 + tid;
        float inv = g[co] / sqrtf(v[co] + BN_EPSF);
        s_sc[tid] = inv;
        s_sh[tid] = cb[co] * inv + (bb[co] - m[co] * inv);
    }
    __syncthreads();
    if (tid < 361) {
        int oy = tid / 19, ox = tid % 19;
        float r[9];
#pragma unroll
        for (int kh = 0; kh < 3; ++kh)
#pragma unroll
            for (int kw = 0; kw < 3; ++kw)
                r[kh * 3 + kw] = s_in[(oy * 2 + kh) * 39 + ox * 2 + kw];
        float* outb = g_h1 + b * 128 * 361 + co0 * 361 + tid;
#pragma unroll 4
        for (int cl = 0; cl < 32; ++cl) {
            float acc = 0.0f;
#pragma unroll
            for (int k = 0; k < 9; ++k) acc = fmaf(r[k], s_w[cl * 9 + k], acc);
            float y = acc * s_sc[cl] + s_sh[cl];
            outb[cl * 361] = y > 0.0f ? y : 0.0f;
        }
    }
}

// ---------------- conv2 weight prep ----------------
__global__ void wtrans_kernel(const float* __restrict__ w2)
{
    int widx = blockIdx.x * 256 + threadIdx.x;
    int n = widx / 576, kp = widx % 576;
    uint32_t lo;
    uint32_t hi = bfsplit_pack_hi(w2[n * 1152 + 2 * kp], w2[n * 1152 + 2 * kp + 1], lo);
    g_wbh[widx] = hi;
    g_wbl[widx] = lo;
}

// ---------------- conv2 implicit GEMM: 144-row m-tiles (288 CTAs = 2 clean waves),
//                  K-chunk 32, A+B double-buffered, 1 sync/chunk, post-barrier B issue ----------------
// smem words: A[2][AH 2880|AL 2880]=11520 | B[2][hi 5120|lo 5120]=20480 | tab 1152 | base 144 | sc 256 | sh 256
#define A_OFF 0
#define A_BUF_STRIDE 5760
#define AL_REL 2880
#define B_OFF 11520
#define B_BUF_STRIDE 10240
#define B_HL_STRIDE 5120
#define TAB_OFF 32000
#define BASE_OFF 33152
#define SC_OFF 33296
#define SH_OFF 33552
#define C2_SMEM_WORDS 33808   // 135,232 bytes

__global__ void __launch_bounds__(576, 1) conv2_mma_kernel(
    const float* __restrict__ cb,
    const float* __restrict__ g, const float* __restrict__ bb,
    const float* __restrict__ m, const float* __restrict__ v)
{
    extern __shared__ uint32_t sm[];
    int*   tabi  = (int*)(sm + TAB_OFF);
    int*   basei = (int*)(sm + BASE_OFF);
    float* ssc   = (float*)(sm + SC_OFF);
    float* ssh   = (float*)(sm + SH_OFF);
    const uint32_t sbase = smem_u32(sm);

    const int tid = threadIdx.x;
    const int w = tid >> 5, lane = tid & 31;
    const int gi = lane >> 2, ti = lane & 3;
    const int mt = blockIdx.x;
    const int r0 = (w >> 1) * 16;         // 9 row slabs (0..128)
    const int c0 = (w & 1) * 128;         // 2 col halves

    for (int k = tid; k < 1152; k += 576) {
        int ci = k / 9, r = k - ci * 9;
        tabi[k] = ci * 361 + (r / 3) * 19 + (r % 3);
    }
    if (tid < 144) {
        int mg = mt * 144 + tid;
        int b = mg / 81, p = mg - b * 81;
        basei[tid] = b * 46208 + (p / 9) * 38 + (p % 9) * 2;
    }
    if (tid < 256) {
        float inv = g[tid] / sqrtf(v[tid] + BN_EPSF);
        ssc[tid] = inv;
        ssh[tid] = cb[tid] * inv + (bb[tid] - m[tid] * inv);
    }
    __syncthreads();

    float d[16][4];
#pragma unroll
    for (int s = 0; s < 16; ++s)
#pragma unroll
        for (int q = 0; q < 4; ++q) d[s][q] = 0.0f;

    const int am = tid >> 2;             // A row (0..143)
    const int akb = (tid & 3) * 8;       // 8 k-elements per thread
    const int awb = (tid & 3) * 4;       // 4 words

    float fr[8];

    // ---- prologue: B(0) cp.async + A(0) gather ----
    {
        if (tid < 512) {
#pragma unroll
            for (int j = 0; j < 4; ++j) {
                int idx = tid + (j << 9);
                int hl = idx >> 10, n = (idx >> 2) & 255, seg = idx & 3;
                const uint32_t* gsrc = (hl ? g_wbl : g_wbh) + n * 576 + seg * 4;
                uint32_t saddr = sbase + (B_OFF + hl * B_HL_STRIDE + n * 20 + seg * 4) * 4;
                cp_async16(saddr, gsrc);
            }
        }
        CP_COMMIT();
        const float* src = g_h1 + basei[am];
        const int* tp = tabi + akb;
#pragma unroll
        for (int j = 0; j < 8; ++j) fr[j] = src[tp[j]];
    }

    for (int ch = 0; ch < 36; ++ch) {
        const int buf = ch & 1;
        // ---- cvt + STS A(ch) ----
        {
            uint32_t* dH = sm + A_OFF + buf * A_BUF_STRIDE + am * 20 + awb;
            uint32_t* dL = dH + AL_REL;
#pragma unroll
            for (int j = 0; j < 4; ++j) {
                uint32_t lo;
                uint32_t hi = bfsplit_pack_hi(fr[2 * j], fr[2 * j + 1], lo);
                dH[j] = hi;
                dL[j] = lo;
            }
        }
        // ---- prefetch A(ch+1) gather ----
        if (ch < 35) {
            const float* src = g_h1 + basei[am];
            const int* tp = tabi + (ch + 1) * 32 + akb;
#pragma unroll
            for (int j = 0; j < 8; ++j) fr[j] = src[tp[j]];
        }
        CP_WAIT0();
        __syncthreads();

        // ---- issue cp.async B(ch+1) into other buffer (overlaps MMA(ch); race-free:
        //      all MMA(ch-1) reads of that buffer precede the barrier above) ----
        if (ch < 35 && tid < 512) {
            const int kp0n = (ch + 1) * 16;
#pragma unroll
            for (int j = 0; j < 4; ++j) {
                int idx = tid + (j << 9);
                int hl = idx >> 10, n = (idx >> 2) & 255, seg = idx & 3;
                const uint32_t* gsrc = (hl ? g_wbl : g_wbh) + n * 576 + kp0n + seg * 4;
                uint32_t saddr = sbase + (B_OFF + (buf ^ 1) * B_BUF_STRIDE + hl * B_HL_STRIDE + n * 20 + seg * 4) * 4;
                cp_async16(saddr, gsrc);
            }
        }
        if (ch < 35) CP_COMMIT();

        // ---- MMA(ch): 2 k16-steps x 16 n-subtiles x 3 terms ----
        const uint32_t* sBh = sm + B_OFF + buf * B_BUF_STRIDE;
        const uint32_t* sBl = sBh + B_HL_STRIDE;
        const uint32_t* AhR = sm + A_OFF + buf * A_BUF_STRIDE + (r0 + gi) * 20;
        const uint32_t* AlR = AhR + AL_REL;
#pragma unroll
        for (int s16 = 0; s16 < 2; ++s16) {
            const int kw = s16 * 8;
            uint32_t ah0 = AhR[kw + ti],          ah1 = AhR[8 * 20 + kw + ti];
            uint32_t ah2 = AhR[kw + ti + 4],      ah3 = AhR[8 * 20 + kw + ti + 4];
            uint32_t al0 = AlR[kw + ti],          al1 = AlR[8 * 20 + kw + ti];
            uint32_t al2 = AlR[kw + ti + 4],      al3 = AlR[8 * 20 + kw + ti + 4];
#pragma unroll
            for (int s = 0; s < 16; ++s) {
                const int br = (c0 + s * 8 + gi) * 20 + kw;
                uint32_t bh0 = sBh[br + ti], bh1 = sBh[br + ti + 4];
                uint32_t bl0 = sBl[br + ti], bl1 = sBl[br + ti + 4];
                asm volatile(
                    "mma.sync.aligned.m16n8k16.row.col.f32.bf16.bf16.f32 "
                    "{%0,%1,%2,%3}, {%4,%5,%6,%7}, {%8,%9}, {%0,%1,%2,%3};"
                    : "+f"(d[s][0]), "+f"(d[s][1]), "+f"(d[s][2]), "+f"(d[s][3])
                    : "r"(ah0), "r"(ah1), "r"(ah2), "r"(ah3), "r"(bh0), "r"(bh1));
                asm volatile(
                    "mma.sync.aligned.m16n8k16.row.col.f32.bf16.bf16.f32 "
                    "{%0,%1,%2,%3}, {%4,%5,%6,%7}, {%8,%9}, {%0,%1,%2,%3};"
                    : "+f"(d[s][0]), "+f"(d[s][1]), "+f"(d[s][2]), "+f"(d[s][3])
                    : "r"(ah0), "r"(ah1), "r"(ah2), "r"(ah3), "r"(bl0), "r"(bl1));
                asm volatile(
                    "mma.sync.aligned.m16n8k16.row.col.f32.bf16.bf16.f32 "
                    "{%0,%1,%2,%3}, {%4,%5,%6,%7}, {%8,%9}, {%0,%1,%2,%3};"
                    : "+f"(d[s][0]), "+f"(d[s][1]), "+f"(d[s][2]), "+f"(d[s][3])
                    : "r"(al0), "r"(al1), "r"(al2), "r"(al3), "r"(bh0), "r"(bh1));
            }
        }
    }

    const int mrow0 = mt * 144 + r0 + gi;
#pragma unroll
    for (int s = 0; s < 16; ++s) {
        int cl = c0 + s * 8 + 2 * ti;
        float sc0 = ssc[cl], sc1 = ssc[cl + 1];
        float sh0 = ssh[cl], sh1 = ssh[cl + 1];
        float v0 = d[s][0] * sc0 + sh0; v0 = v0 > 0.0f ? v0 : 0.0f;
        float v1 = d[s][1] * sc1 + sh1; v1 = v1 > 0.0f ? v1 : 0.0f;
        float v2 = d[s][2] * sc0 + sh0; v2 = v2 > 0.0f ? v2 : 0.0f;
        float v3 = d[s][3] * sc1 + sh1; v3 = v3 > 0.0f ? v3 : 0.0f;
        *(float2*)(g_h2 + (size_t)mrow0 * 256 + cl)       = make_float2(v0, v1);
        *(float2*)(g_h2 + (size_t)(mrow0 + 8) * 256 + cl) = make_float2(v2, v3);
    }
}

// ---------------- conv3 (depthwise 9x9) + squash -> g_u ----------------
__global__ void conv3s_kernel(const float* __restrict__ w3, const float* __restrict__ b3)
{
    int b = blockIdx.x, c = threadIdx.x;
    const float* h2b = g_h2 + b * 81 * 256;
    float acc = 0.0f;
#pragma unroll
    for (int p = 0; p < 81; ++p)
        acc = fmaf(h2b[p * 256 + c], w3[c * 81 + p], acc);
    acc += b3[c];

    float sq = acc * acc;
    sq += __shfl_xor_sync(0xffffffffu, sq, 4);
    sq += __shfl_xor_sync(0xffffffffu, sq, 2);
    sq += __shfl_xor_sync(0xffffffffu, sq, 1);
    float nrm = sqrtf(sq);
    float t1 = 1.0f - 1.0f / (exp_matched(nrm) + EPSF);
    g_u[b * 256 + c] = t1 * (acc / (nrm + EPSF));
}

// ---------------- U_hat GEMM ----------------
template<int NH, int DH>
__global__ void __launch_bounds__(256) uhat_kernel(const float* __restrict__ W)
{
    constexpr int NHDH = NH * DH;
    __shared__ float sW[8 * NHDH];
    __shared__ float sUb[64 * 8];
    const int i = blockIdx.x;
    const int b0 = blockIdx.y * 64;
    const int tid = threadIdx.x;

    for (int idx = tid; idx < 8 * NHDH; idx += 256) {
        int k = idx / (8 * DH);
        int r = idx % (8 * DH);
        int j = r / DH, l = r % DH;
        sW[j * NHDH + k * DH + l] = W[i * NH * 8 * DH + idx];
    }
    for (int idx = tid; idx < 512; idx += 256) {
        int bb = idx >> 3, j = idx & 7;
        sUb[idx] = g_u[(b0 + bb) * 256 + i * 8 + j];
    }
    __syncthreads();

    if (tid < NHDH) {
        float wr[8];
#pragma unroll
        for (int j = 0; j < 8; ++j) wr[j] = sW[j * NHDH + tid];
        float* dst = g_uhat + (size_t)b0 * (32 * NHDH) + i * NHDH + tid;
#pragma unroll 4
        for (int bb = 0; bb < 64; ++bb) {
            const float* u = sUb + bb * 8;
            float a = 0.0f;
#pragma unroll
            for (int j = 0; j < 8; ++j) a = fmaf(u[j], wr[j], a);
            dst[(size_t)bb * (32 * NHDH)] = a;
        }
    }
}

// ---------------- attention + squash ----------------
template<int NH, int DH, bool FINAL>
__global__ void __launch_bounds__(256) attn_kernel(float* __restrict__ outp)
{
    constexpr int NHDH = NH * DH;
    constexpr int NL = 32;
    __shared__ float sUhat[NL * NHDH];
    __shared__ float sS[NHDH];
    __shared__ float sA[NL * NH];
    const int b = blockIdx.x, tid = threadIdx.x;

    if (tid < NHDH) {
        const float* src = g_uhat + (size_t)b * (NL * NHDH) + tid;
        float ssum = 0.0f;
#pragma unroll
        for (int i = 0; i < NL; ++i) {
            float vv = src[i * NHDH];
            sUhat[i * NHDH + tid] = vv;
            ssum += vv;
        }
        sS[tid] = ssum;
    }
    __syncthreads();

    for (int idx = tid; idx < NL * NH; idx += 256) {
        int i = idx / NH, k = idx % NH;
        float a = 0.0f;
#pragma unroll
        for (int l = 0; l < DH; ++l) a = fmaf(sS[k * DH + l], sUhat[i * NHDH + k * DH + l], a);
        sA[idx] = a * INV_ATTN;
    }
    __syncthreads();

    {
        int wid = tid >> 5, lane = tid & 31;
#pragma unroll
        for (int q = 0; q < 4; ++q) {
            int i = wid * 4 + q;
            float val = (lane < NH) ? sA[i * NH + lane] : -1e30f;
            float mx = val;
#pragma unroll
            for (int o = 16; o; o >>= 1) mx = fmaxf(mx, __shfl_xor_sync(0xffffffffu, mx, o));
            float e = (lane < NH) ? expf(val - mx) : 0.0f;
            float sum = e;
#pragma unroll
            for (int o = 16; o; o >>= 1) sum += __shfl_xor_sync(0xffffffffu, sum, o);
            if (lane < NH) sA[i * NH + lane] = e / sum;
        }
    }
    __syncthreads();

    if (tid < NHDH) {
        int k = tid / DH;
        float acc = 0.0f;
#pragma unroll
        for (int i = 0; i < NL; ++i) acc = fmaf(sA[i * NH + k], sUhat[i * NHDH + tid], acc);
        float sq = acc * acc;
#pragma unroll
        for (int o = DH / 2; o; o >>= 1) sq += __shfl_xor_sync(0xffffffffu, sq, o);
        float nrm = sqrtf(sq);
        float t1 = 1.0f - 1.0f / (exp_matched(nrm) + EPSF);
        float val = t1 * (acc / (nrm + EPSF));
        if (FINAL) outp[(size_t)b * NHDH + tid] = val;
        else       g_u[(size_t)b * 256 + tid] = val;
    }
}

// ---------------- launch ----------------
extern "C" void kernel_launch(void* const* d_in, const int* in_sizes, int n_in,
                              void* d_out, int out_size)
{
    const float* x       = (const float*)d_in[0];
    const float* conv1_w = (const float*)d_in[1];
    const float* conv1_b = (const float*)d_in[2];
    const float* bn1_g   = (const float*)d_in[3];
    const float* bn1_b   = (const float*)d_in[4];
    const float* bn1_m   = (const float*)d_in[5];
    const float* bn1_v   = (const float*)d_in[6];
    const float* conv2_w = (const float*)d_in[7];
    const float* conv2_b = (const float*)d_in[8];
    const float* bn2_g   = (const float*)d_in[9];
    const float* bn2_b   = (const float*)d_in[10];
    const float* bn2_m   = (const float*)d_in[11];
    const float* bn2_v   = (const float*)d_in[12];
    const float* conv3_w = (const float*)d_in[13];
    const float* conv3_b = (const float*)d_in[14];
    const float* W1      = (const float*)d_in[15];
    const float* W2      = (const float*)d_in[16];
    const float* W3      = (const float*)d_in[17];
    float* out = (float*)d_out;

    cudaFuncSetAttribute(conv2_mma_kernel, cudaFuncAttributeMaxDynamicSharedMemorySize,
                         C2_SMEM_WORDS * (int)sizeof(uint32_t));

    conv1_kernel<<<dim3(NB, 4), 384>>>(x, conv1_w, conv1_b, bn1_g, bn1_b, bn1_m, bn1_v);
    wtrans_kernel<<<576, 256>>>(conv2_w);
    conv2_mma_kernel<<<288, 576, C2_SMEM_WORDS * sizeof(uint32_t)>>>(
        conv2_b, bn2_g, bn2_b, bn2_m, bn2_v);
    conv3s_kernel<<<NB, 256>>>(conv3_w, conv3_b);

    uhat_kernel<32, 8><<<dim3(32, 8), 256>>>(W1);
    attn_kernel<32, 8, false><<<NB, 256>>>(nullptr);
    uhat_kernel<32, 8><<<dim3(32, 8), 256>>>(W2);
    attn_kernel<32, 8, false><<<NB, 256>>>(nullptr);
    uhat_kernel<10, 16><<<dim3(32, 8), 256>>>(W3);
    attn_kernel<10, 16, true><<<NB, 256>>>(out);
}